// round 8
// baseline (speedup 1.0000x reference)
#include <cuda_runtime.h>
#include <cuda_bf16.h>
#include <math.h>
#include <stdint.h>

#define TPB   256
#define MT    128
#define DIN   512
#define HH    50
#define DOUT  128
#define MAXN  0.996f
#define MINN  1e-15f

typedef unsigned long long ull;
typedef uint32_t u32;

// ---- smem byte offsets ----
#define OFF_X0H   0
#define OFF_X1H   36864
#define OFF_W10H  73728
#define OFF_W11H  92160
// aliases (live after GEMM1 finishes):
#define OFF_MXS   0          // mx f32 [128][65]
#define OFF_W3H   36864      // W3 hi (Xbuf1 hi half)
#define OFF_W3L   55296
#define OFF_UH    73728      // u hi (W1 buf region)
#define OFF_UL    92160
// persistent extras
#define OFF_HB1   110592
#define OFF_HB3   110848
#define OFF_X2S   111360
#define OFF_UNS   112384
#define SMEM_BYTES 112896

__device__ float g_hb1[64];
__device__ float g_hb3[128];
__device__ float g_hb1sq, g_hb3sq;
__device__ __align__(16) __nv_bfloat16 g_w1h[64 * 512];   // rows 50..63 zero
__device__ __align__(16) __nv_bfloat16 g_w1l[64 * 512];
__device__ __align__(16) __nv_bfloat16 g_w3h[128 * 64];   // k 50..63 zero
__device__ __align__(16) __nv_bfloat16 g_w3l[128 * 64];

__device__ __forceinline__ float artanh_c(float z) {
    z = fminf(z, 1.0f - 1e-7f);
    return 0.5f * logf((1.0f + z) / (1.0f - z));
}

// ---- HMMA / async helpers ----
__device__ __forceinline__ void mma_bf16(float* d, const u32* a, const u32* b) {
    asm("mma.sync.aligned.m16n8k16.row.col.f32.bf16.bf16.f32 "
        "{%0,%1,%2,%3}, {%4,%5,%6,%7}, {%8,%9}, {%0,%1,%2,%3};"
        : "+f"(d[0]), "+f"(d[1]), "+f"(d[2]), "+f"(d[3])
        : "r"(a[0]), "r"(a[1]), "r"(a[2]), "r"(a[3]), "r"(b[0]), "r"(b[1]));
}
__device__ __forceinline__ void ldsm4(u32* r, u32 addr) {
    asm volatile("ldmatrix.sync.aligned.m8n8.x4.shared.b16 {%0,%1,%2,%3}, [%4];"
        : "=r"(r[0]), "=r"(r[1]), "=r"(r[2]), "=r"(r[3]) : "r"(addr));
}
// truncation split of two floats -> packed bf16x2 hi (exact prefix) + bf16x2 lo
__device__ __forceinline__ void split2(float a, float b, u32& hi, u32& lo) {
    u32 ua = __float_as_uint(a), ub = __float_as_uint(b);
    u32 h;
    asm("prmt.b32 %0, %1, %2, 0x7632;" : "=r"(h) : "r"(ua), "r"(ub));
    float ha = __uint_as_float(ua & 0xFFFF0000u);
    float hb = __uint_as_float(ub & 0xFFFF0000u);
    float la = a - ha, lb = b - hb;
    u32 l;
    asm("cvt.rn.bf16x2.f32 %0, %1, %2;" : "=r"(l) : "f"(lb), "f"(la));
    hi = h; lo = l;
}
__device__ __forceinline__ void cp_async16(u32 sdst, const void* gsrc) {
    asm volatile("cp.async.ca.shared.global [%0], [%1], 16;" :: "r"(sdst), "l"(gsrc));
}
__device__ __forceinline__ void cp_wait_all() {
    asm volatile("cp.async.commit_group;\n\tcp.async.wait_group 0;" ::: "memory");
}

// merged setup: W1/W3 bf16 hi-lo conversion (grid-stride) + bias precompute (block 0)
__global__ void setup_kernel(const float* __restrict__ W1, const float* __restrict__ W3,
                             const float* __restrict__ b1, const float* __restrict__ b3) {
    for (int idx = blockIdx.x * blockDim.x + threadIdx.x;
         idx < 64 * 512 + 128 * 64; idx += gridDim.x * blockDim.x) {
        if (idx < 64 * 512) {
            int row = idx >> 9;
            float v = (row < HH) ? W1[(size_t)row * DIN + (idx & 511)] : 0.0f;
            u32 uh = __float_as_uint(v) & 0xFFFF0000u;
            g_w1h[idx] = __ushort_as_bfloat16((unsigned short)(uh >> 16));
            g_w1l[idx] = __float2bfloat16(v - __uint_as_float(uh));
        } else {
            int i = idx - 64 * 512;
            int k = i & 63;
            float v = (k < HH) ? W3[(size_t)(i >> 6) * HH + k] : 0.0f;
            u32 uh = __float_as_uint(v) & 0xFFFF0000u;
            g_w3h[i] = __ushort_as_bfloat16((unsigned short)(uh >> 16));
            g_w3l[i] = __float2bfloat16(v - __uint_as_float(uh));
        }
    }
    if (blockIdx.x == 0) {
        __shared__ float s[256];
        int t = threadIdx.x;

        float v1 = (t < HH) ? b1[t] : 0.0f;
        s[t] = v1 * v1;
        __syncthreads();
        for (int o = 128; o > 0; o >>= 1) { if (t < o) s[t] += s[t + o]; __syncthreads(); }
        float nb2 = s[0];
        __syncthreads();
        {
            float nb = fmaxf(sqrtf(nb2), MINN);
            float th = tanhf(nb);
            float sc = th / nb;
            if (th > MAXN) { sc *= MAXN / th; th = MAXN; }
            if (t < HH) g_hb1[t] = sc * v1;
            if (t == 0) g_hb1sq = th * th;
        }

        float v3 = (t < DOUT) ? b3[t] : 0.0f;
        s[t] = v3 * v3;
        __syncthreads();
        for (int o = 128; o > 0; o >>= 1) { if (t < o) s[t] += s[t + o]; __syncthreads(); }
        nb2 = s[0];
        __syncthreads();
        {
            float nb = fmaxf(sqrtf(nb2), MINN);
            float th = tanhf(nb);
            float sc = th / nb;
            if (th > MAXN) { sc *= MAXN / th; th = MAXN; }
            if (t < DOUT) g_hb3[t] = sc * v3;
            if (t == 0) g_hb3sq = th * th;
        }
    }
}

extern __shared__ __align__(1024) char smraw[];

__global__ __launch_bounds__(TPB, 2)
void hnn_kernel(const float* __restrict__ X, float* __restrict__ out, int N, int nTiles)
{
    const u32 sb = (u32)__cvta_generic_to_shared(smraw);
    float* mxs  = (float*)(smraw + OFF_MXS);
    float* hb1s = (float*)(smraw + OFF_HB1);
    float* hb3s = (float*)(smraw + OFF_HB3);
    float* x2s  = (float*)(smraw + OFF_X2S);
    float* un_s = (float*)(smraw + OFF_UNS);

    const int tid = threadIdx.x;
    const int lane = tid & 31;
    const int c = tid >> 5;
    const int mg = c & 3;
    const int ng = c >> 2;

    for (int i = tid; i < 64; i += TPB) hb1s[i] = (i < HH) ? g_hb1[i] : 0.0f;
    if (tid < DOUT) hb3s[tid] = g_hb3[tid];
    const float hb1sq = g_hb1sq;
    const float hb3sq = g_hb3sq;

    const int xrow = tid & 127;
    const int xkh  = tid >> 7;
    const u32 xoff = (u32)(xrow * 144 + xkh * 64);
    const u32 aRow = (u32)(mg * 32 + (lane & 15));
    const u32 aKof = (u32)((lane >> 4) * 16);
    const u32 bN   = (u32)(ng * 32 + ((lane >> 4) * 8) + (lane & 7));
    const u32 bKof = (u32)(((lane >> 3) & 1) * 16);
    const u32 a2H = sb + OFF_UH + (u32)((c * 16 + (lane & 15)) * 144 + (lane >> 4) * 16);
    const u32 a2L = a2H + 18432u;
    const u32 b2H = sb + OFF_W3H + (u32)((((lane >> 4) * 8) + (lane & 7)) * 144 + ((lane >> 3) & 1) * 16);
    const u32 b2L = b2H + 18432u;
    const int g2 = lane >> 2, t2 = lane & 3;

    u32 w1_rel[4];
    const __nv_bfloat16* w1_gsrc[4];
#pragma unroll
    for (int p = 0; p < 4; p++) {
        int u = tid + 256 * p;
        int half = u >> 9, n = (u >> 3) & 63, j = u & 7;
        w1_rel[p] = (u32)(half * 9216 + n * 144 + j * 16);
        w1_gsrc[p] = (half ? g_w1l : g_w1h) + n * 512 + j * 8;
    }

    for (int tile = blockIdx.x; tile < nTiles; tile += gridDim.x) {
        const int baseRow = tile * MT;
        const int gr = baseRow + xrow;
        const bool valid = gr < N;
        const float* xptr = X + (size_t)gr * DIN + xkh * 32;
        float x2a = 0.0f;

        float4 xr[8];
#pragma unroll
        for (int q = 0; q < 8; q++)
            xr[q] = valid ? *(const float4*)(xptr + q * 4) : make_float4(0.f, 0.f, 0.f, 0.f);

        __syncthreads();   // prior tile's GEMM2 reads (U, W3 aliases) complete

        float acc[2][4][4];
#pragma unroll
        for (int mt = 0; mt < 2; mt++)
#pragma unroll
            for (int nt = 0; nt < 4; nt++)
#pragma unroll
                for (int e = 0; e < 4; e++) acc[mt][nt][e] = 0.0f;

        // ---- prologue: stage chunk 0 into buf0; prefetch chunk 1 ----
#pragma unroll
        for (int q = 0; q < 8; q += 2) {
            float4 v0 = xr[q], v1 = xr[q + 1];
            u32 h0, h1, h2, h3, l0, l1, l2, l3;
            split2(v0.x, v0.y, h0, l0);
            split2(v0.z, v0.w, h1, l1);
            split2(v1.x, v1.y, h2, l2);
            split2(v1.z, v1.w, h3, l3);
            *(uint4*)(smraw + OFF_X0H + xoff + q * 8) = make_uint4(h0, h1, h2, h3);
            *(uint4*)(smraw + OFF_X0H + 18432 + xoff + q * 8) = make_uint4(l0, l1, l2, l3);
            x2a = fmaf(v0.x, v0.x, fmaf(v0.y, v0.y, fmaf(v0.z, v0.z, fmaf(v0.w, v0.w, x2a))));
            x2a = fmaf(v1.x, v1.x, fmaf(v1.y, v1.y, fmaf(v1.z, v1.z, fmaf(v1.w, v1.w, x2a))));
        }
#pragma unroll
        for (int p = 0; p < 4; p++)
            cp_async16(sb + OFF_W10H + w1_rel[p], w1_gsrc[p]);
#pragma unroll
        for (int q = 0; q < 8; q++)
            xr[q] = valid ? *(const float4*)(xptr + 64 + q * 4) : make_float4(0.f, 0.f, 0.f, 0.f);
        cp_wait_all();
        __syncthreads();

        // ---- main loop: stage(kc+1) co-scheduled with mma(kc), one barrier/chunk ----
        for (int kc = 0; kc < 8; kc++) {
            const u32 bX = (u32)((kc & 1) ? OFF_X1H : OFF_X0H);
            const u32 bW = (u32)((kc & 1) ? OFF_W11H : OFF_W10H);

            if (kc < 7) {
                const u32 nX = (u32)((kc & 1) ? OFF_X0H : OFF_X1H);
                const u32 nW = (u32)((kc & 1) ? OFF_W10H : OFF_W11H);
#pragma unroll
                for (int q = 0; q < 8; q += 2) {
                    float4 v0 = xr[q], v1 = xr[q + 1];
                    u32 h0, h1, h2, h3, l0, l1, l2, l3;
                    split2(v0.x, v0.y, h0, l0);
                    split2(v0.z, v0.w, h1, l1);
                    split2(v1.x, v1.y, h2, l2);
                    split2(v1.z, v1.w, h3, l3);
                    *(uint4*)(smraw + nX + xoff + q * 8) = make_uint4(h0, h1, h2, h3);
                    *(uint4*)(smraw + nX + 18432 + xoff + q * 8) = make_uint4(l0, l1, l2, l3);
                    x2a = fmaf(v0.x, v0.x, fmaf(v0.y, v0.y, fmaf(v0.z, v0.z, fmaf(v0.w, v0.w, x2a))));
                    x2a = fmaf(v1.x, v1.x, fmaf(v1.y, v1.y, fmaf(v1.z, v1.z, fmaf(v1.w, v1.w, x2a))));
                }
#pragma unroll
                for (int p = 0; p < 4; p++)
                    cp_async16(sb + nW + w1_rel[p], w1_gsrc[p] + (kc + 1) * 64);
                if (kc < 6) {
#pragma unroll
                    for (int q = 0; q < 8; q++)
                        xr[q] = valid ? *(const float4*)(xptr + (kc + 2) * 64 + q * 4)
                                      : make_float4(0.f, 0.f, 0.f, 0.f);
                }
            }

            // MMAs over buffer kc (overlaps other warps' staging)
#pragma unroll
            for (int k16 = 0; k16 < 4; k16++) {
                u32 bh[8], bl[8];
#pragma unroll
                for (int np = 0; np < 2; np++) {
                    u32 boff = (bN + (u32)(np * 16)) * 144u + (u32)(k16 * 32) + bKof;
                    ldsm4(bh + np * 4, sb + bW + boff);
                    ldsm4(bl + np * 4, sb + bW + 9216 + boff);
                }
#pragma unroll
                for (int mt = 0; mt < 2; mt++) {
                    u32 aoff = (aRow + (u32)(mt * 16)) * 144u + (u32)(k16 * 32) + aKof;
                    u32 ah[4], al[4];
                    ldsm4(ah, sb + bX + aoff);
                    ldsm4(al, sb + bX + 18432 + aoff);
#pragma unroll
                    for (int nt = 0; nt < 4; nt++) {
                        mma_bf16(acc[mt][nt], ah, bh + nt * 2);
                        mma_bf16(acc[mt][nt], al, bh + nt * 2);
                        mma_bf16(acc[mt][nt], ah, bl + nt * 2);
                    }
                }
            }
            cp_wait_all();
            __syncthreads();
        }

        // spill fragments to mxs (Xbuf0 alias; its chunk data is dead)
        {
            int g = lane >> 2, t = lane & 3;
#pragma unroll
            for (int mt = 0; mt < 2; mt++) {
                int r0 = mg * 32 + mt * 16 + g;
#pragma unroll
                for (int nt = 0; nt < 4; nt++) {
                    int col = ng * 32 + nt * 8 + t * 2;
                    mxs[r0 * 65 + col]           = acc[mt][nt][0];
                    mxs[r0 * 65 + col + 1]       = acc[mt][nt][1];
                    mxs[(r0 + 8) * 65 + col]     = acc[mt][nt][2];
                    mxs[(r0 + 8) * 65 + col + 1] = acc[mt][nt][3];
                }
            }
        }
        x2s[xkh * 128 + xrow] = x2a;
        __syncthreads();

        // stage W3 hi/lo into Xbuf1 alias (hidden under epilogue 1)
        for (int i = tid; i < 1024; i += TPB) {
            int n = i >> 3, j = i & 7;
            cp_async16(sb + OFF_W3H + (u32)(n * 144 + j * 16), g_w3h + n * 64 + j * 8);
            cp_async16(sb + OFF_W3L + (u32)(n * 144 + j * 16), g_w3l + n * 64 + j * 8);
        }

        // -------- Epilogue 1 (threads 0..127, one per row) --------
        if (tid < 128) {
            const int r0 = tid;
            float sx2 = x2s[r0] + x2s[128 + r0];
            float nx = fmaxf(sqrtf(sx2), MINN);
            float th = tanhf(nx);
            float al = th / nx;
            float xn1 = fmaxf(th, MINN);

            float p0 = 0.f, p1 = 0.f;
#pragma unroll
            for (int j = 0; j < HH; j++) {
                float v = al * mxs[r0 * 65 + j];
                p0 = fmaf(v, v, p0);
                p1 = fmaf(v, hb1s[j], p1);
            }
            float mxn = fmaxf(sqrtf(p0), MINN);
            float art = artanh_c(xn1);
            float t = tanhf(mxn / xn1 * art);
            float g = t / mxn;
            float rn = t;
            if (rn > MAXN) { g *= MAXN / rn; rn = MAXN; }
            float xy = g * p1;
            float x2 = rn * rn;
            float den = fmaxf(1.0f + 2.0f * xy + x2 * hb1sq, MINN);
            float A = (1.0f + 2.0f * xy + hb1sq) / den;
            float B = (1.0f - x2) / den;
            float nv2 = A * A * x2 + 2.0f * A * B * xy + B * B * hb1sq;
            float nv = sqrtf(nv2);
            float pf = (nv > MAXN) ? (MAXN / nv) : 1.0f;
            nv = fminf(nv, MAXN);
            float beta = artanh_c(nv) / fmaxf(nv, MINN);
            float C1a = beta * pf * A * g * al;
            float C2 = beta * pf * B;

            float xt_buf[HH];
            float p = 0.f;
#pragma unroll
            for (int j = 0; j < HH; j++) {
                float xt = C1a * mxs[r0 * 65 + j] + C2 * hb1s[j];
                xt = (xt > 0.0f) ? xt : 0.01f * xt;
                xt_buf[j] = xt;
                p = fmaf(xt, xt, p);
            }
            float nxt = fmaxf(sqrtf(p), MINN);
            float t3 = tanhf(nxt);
            float gam = t3 / nxt;
            if (t3 > MAXN) { gam *= MAXN / t3; t3 = MAXN; }
            un_s[r0] = fmaxf(t3, MINN);

#pragma unroll
            for (int jj = 0; jj < 25; jj++) {
                float v0 = gam * xt_buf[jj * 2];
                float v1 = (jj * 2 + 1 < HH) ? gam * xt_buf[jj * 2 + 1] : 0.0f;
                u32 h, l;
                split2(v0, v1, h, l);
                *(u32*)(smraw + OFF_UH + r0 * 144 + jj * 4) = h;
                *(u32*)(smraw + OFF_UL + r0 * 144 + jj * 4) = l;
            }
#pragma unroll
            for (int jj = 25; jj < 32; jj++) {
                *(u32*)(smraw + OFF_UH + r0 * 144 + jj * 4) = 0u;
                *(u32*)(smraw + OFF_UL + r0 * 144 + jj * 4) = 0u;
            }
        }
        cp_wait_all();
        __syncthreads();

        // -------- GEMM2: u @ W3^T (HMMA bf16, 3-way split; 16 rows/warp) --------
        float acc2[16][4];
#pragma unroll
        for (int nt = 0; nt < 16; nt++)
#pragma unroll
            for (int e = 0; e < 4; e++) acc2[nt][e] = 0.0f;

#pragma unroll
        for (int k16 = 0; k16 < 4; k16++) {
            u32 ah[4], al[4];
            ldsm4(ah, a2H + (u32)(k16 * 32));
            ldsm4(al, a2L + (u32)(k16 * 32));
#pragma unroll
            for (int np = 0; np < 8; np++) {
                u32 bh[4], bl[4];
                u32 boff = (u32)(np * 2304 + k16 * 32);
                ldsm4(bh, b2H + boff);
                ldsm4(bl, b2L + boff);
#pragma unroll
                for (int npi = 0; npi < 2; npi++) {
                    mma_bf16(acc2[np * 2 + npi], ah, bh + npi * 2);
                    mma_bf16(acc2[np * 2 + npi], al, bh + npi * 2);
                    mma_bf16(acc2[np * 2 + npi], ah, bl + npi * 2);
                }
            }
        }

        float hb3v[32];
#pragma unroll
        for (int nt = 0; nt < 16; nt++) {
            float2 hv = *(float2*)(hb3s + nt * 8 + t2 * 2);
            hb3v[nt * 2] = hv.x; hb3v[nt * 2 + 1] = hv.y;
        }
        float p0a = 0.f, p1a = 0.f, p0b = 0.f, p1b = 0.f;
#pragma unroll
        for (int nt = 0; nt < 16; nt++) {
            p0a = fmaf(acc2[nt][0], acc2[nt][0], fmaf(acc2[nt][1], acc2[nt][1], p0a));
            p1a = fmaf(acc2[nt][0], hb3v[nt * 2], fmaf(acc2[nt][1], hb3v[nt * 2 + 1], p1a));
            p0b = fmaf(acc2[nt][2], acc2[nt][2], fmaf(acc2[nt][3], acc2[nt][3], p0b));
            p1b = fmaf(acc2[nt][2], hb3v[nt * 2], fmaf(acc2[nt][3], hb3v[nt * 2 + 1], p1b));
        }
#pragma unroll
        for (int o = 1; o <= 2; o <<= 1) {
            p0a += __shfl_xor_sync(0xffffffffu, p0a, o);
            p1a += __shfl_xor_sync(0xffffffffu, p1a, o);
            p0b += __shfl_xor_sync(0xffffffffu, p0b, o);
            p1b += __shfl_xor_sync(0xffffffffu, p1b, o);
        }

        const int row1 = c * 16 + g2;
        const int row2 = row1 + 8;
        float cA1, cB1, cA2, cB2;
        {
            float un = un_s[row1];
            float mxn = fmaxf(sqrtf(p0a), MINN);
            float art = artanh_c(un);
            float t = tanhf(mxn / un * art);
            float g = t / mxn;
            float rn = t;
            if (rn > MAXN) { g *= MAXN / rn; rn = MAXN; }
            float xy = g * p1a;
            float x2 = rn * rn;
            float den = fmaxf(1.0f + 2.0f * xy + x2 * hb3sq, MINN);
            float A = (1.0f + 2.0f * xy + hb3sq) / den;
            float B = (1.0f - x2) / den;
            float nv = sqrtf(A * A * x2 + 2.0f * A * B * xy + B * B * hb3sq);
            float pf = (nv > MAXN) ? (MAXN / nv) : 1.0f;
            cA1 = pf * A * g; cB1 = pf * B;
        }
        {
            float un = un_s[row2];
            float mxn = fmaxf(sqrtf(p0b), MINN);
            float art = artanh_c(un);
            float t = tanhf(mxn / un * art);
            float g = t / mxn;
            float rn = t;
            if (rn > MAXN) { g *= MAXN / rn; rn = MAXN; }
            float xy = g * p1b;
            float x2 = rn * rn;
            float den = fmaxf(1.0f + 2.0f * xy + x2 * hb3sq, MINN);
            float A = (1.0f + 2.0f * xy + hb3sq) / den;
            float B = (1.0f - x2) / den;
            float nv = sqrtf(A * A * x2 + 2.0f * A * B * xy + B * B * hb3sq);
            float pf = (nv > MAXN) ? (MAXN / nv) : 1.0f;
            cA2 = pf * A * g; cB2 = pf * B;
        }

        {
            int g1r = baseRow + row1;
            int g2r = baseRow + row2;
            if (g1r < N) {
                float* o1 = out + (size_t)g1r * DOUT + t2 * 2;
#pragma unroll
                for (int nt = 0; nt < 16; nt++) {
                    float2 v;
                    v.x = cA1 * acc2[nt][0] + cB1 * hb3v[nt * 2];
                    v.y = cA1 * acc2[nt][1] + cB1 * hb3v[nt * 2 + 1];
                    *(float2*)(o1 + nt * 8) = v;
                }
            }
            if (g2r < N) {
                float* o2 = out + (size_t)g2r * DOUT + t2 * 2;
#pragma unroll
                for (int nt = 0; nt < 16; nt++) {
                    float2 v;
                    v.x = cA2 * acc2[nt][2] + cB2 * hb3v[nt * 2];
                    v.y = cA2 * acc2[nt][3] + cB2 * hb3v[nt * 2 + 1];
                    *(float2*)(o2 + nt * 8) = v;
                }
            }
        }
    }
}

extern "C" void kernel_launch(void* const* d_in, const int* in_sizes, int n_in,
                              void* d_out, int out_size) {
    const float* x  = (const float*)d_in[0];
    const float* W1 = (const float*)d_in[1];
    const float* b1 = (const float*)d_in[2];
    const float* W3 = (const float*)d_in[3];
    const float* b3 = (const float*)d_in[4];
    float* out = (float*)d_out;
    int N = in_sizes[0] / DIN;
    int nTiles = (N + MT - 1) / MT;
    int grid = nTiles < 296 ? nTiles : 296;

    cudaFuncSetAttribute(hnn_kernel, cudaFuncAttributeMaxDynamicSharedMemorySize, SMEM_BYTES);

    setup_kernel<<<161, 256>>>(W1, W3, b1, b3);
    hnn_kernel<<<grid, TPB, SMEM_BYTES>>>(x, out, N, nTiles);
}

// round 9
// speedup vs baseline: 1.0602x; 1.0602x over previous
#include <cuda_runtime.h>
#include <cuda_bf16.h>
#include <math.h>
#include <stdint.h>

#define TPB   256
#define MT    128
#define DIN   512
#define HH    50
#define DOUT  128
#define MAXN  0.996f
#define MINN  1e-15f

typedef unsigned long long ull;
typedef uint32_t u32;

// ---- smem byte offsets ----
// W1 staging double buffer occupies [0, 36864); U (bf16 hi/lo) aliases it after GEMM1.
#define OFF_UH    0
#define OFF_UL    18432
#define OFF_MXS   36864      // mx f32 [128][65] = 33280
#define OFF_W3H   70144      // W3 hi 128x144 (resident)
#define OFF_W3L   88576
#define OFF_HB1   107008     // 64 f32
#define OFF_HB3   107264     // 128 f32
#define OFF_X2S   107776     // 128 f32
#define OFF_UNS   108288     // 128 f32
#define SMEM_BYTES 108800

__device__ float g_hb1[64];
__device__ float g_hb3[128];
__device__ float g_hb1sq, g_hb3sq;
__device__ __align__(16) __nv_bfloat16 g_w1h[64 * 512];   // rows 50..63 zero
__device__ __align__(16) __nv_bfloat16 g_w1l[64 * 512];
__device__ __align__(16) __nv_bfloat16 g_w3h[128 * 64];   // k 50..63 zero
__device__ __align__(16) __nv_bfloat16 g_w3l[128 * 64];

__device__ __forceinline__ float artanh_c(float z) {
    z = fminf(z, 1.0f - 1e-7f);
    return 0.5f * logf((1.0f + z) / (1.0f - z));
}

// ---- HMMA / async helpers ----
__device__ __forceinline__ void mma_bf16(float* d, const u32* a, const u32* b) {
    asm("mma.sync.aligned.m16n8k16.row.col.f32.bf16.bf16.f32 "
        "{%0,%1,%2,%3}, {%4,%5,%6,%7}, {%8,%9}, {%0,%1,%2,%3};"
        : "+f"(d[0]), "+f"(d[1]), "+f"(d[2]), "+f"(d[3])
        : "r"(a[0]), "r"(a[1]), "r"(a[2]), "r"(a[3]), "r"(b[0]), "r"(b[1]));
}
__device__ __forceinline__ void ldsm4(u32* r, u32 addr) {
    asm volatile("ldmatrix.sync.aligned.m8n8.x4.shared.b16 {%0,%1,%2,%3}, [%4];"
        : "=r"(r[0]), "=r"(r[1]), "=r"(r[2]), "=r"(r[3]) : "r"(addr));
}
// truncation split of two floats -> packed bf16x2 hi (exact prefix) + bf16x2 lo
__device__ __forceinline__ void split2(float a, float b, u32& hi, u32& lo) {
    u32 ua = __float_as_uint(a), ub = __float_as_uint(b);
    u32 h;
    asm("prmt.b32 %0, %1, %2, 0x7632;" : "=r"(h) : "r"(ua), "r"(ub));
    float ha = __uint_as_float(ua & 0xFFFF0000u);
    float hb = __uint_as_float(ub & 0xFFFF0000u);
    float la = a - ha, lb = b - hb;
    u32 l;
    asm("cvt.rn.bf16x2.f32 %0, %1, %2;" : "=r"(l) : "f"(lb), "f"(la));
    hi = h; lo = l;
}
__device__ __forceinline__ void cp_async16(u32 sdst, const void* gsrc) {
    asm volatile("cp.async.ca.shared.global [%0], [%1], 16;" :: "r"(sdst), "l"(gsrc));
}
__device__ __forceinline__ void cp_wait_all() {
    asm volatile("cp.async.commit_group;\n\tcp.async.wait_group 0;" ::: "memory");
}

// merged setup: W1/W3 bf16 hi-lo conversion (grid-stride) + bias precompute (block 0)
__global__ void setup_kernel(const float* __restrict__ W1, const float* __restrict__ W3,
                             const float* __restrict__ b1, const float* __restrict__ b3) {
    for (int idx = blockIdx.x * blockDim.x + threadIdx.x;
         idx < 64 * 512 + 128 * 64; idx += gridDim.x * blockDim.x) {
        if (idx < 64 * 512) {
            int row = idx >> 9;
            float v = (row < HH) ? W1[(size_t)row * DIN + (idx & 511)] : 0.0f;
            u32 uh = __float_as_uint(v) & 0xFFFF0000u;
            g_w1h[idx] = __ushort_as_bfloat16((unsigned short)(uh >> 16));
            g_w1l[idx] = __float2bfloat16(v - __uint_as_float(uh));
        } else {
            int i = idx - 64 * 512;
            int k = i & 63;
            float v = (k < HH) ? W3[(size_t)(i >> 6) * HH + k] : 0.0f;
            u32 uh = __float_as_uint(v) & 0xFFFF0000u;
            g_w3h[i] = __ushort_as_bfloat16((unsigned short)(uh >> 16));
            g_w3l[i] = __float2bfloat16(v - __uint_as_float(uh));
        }
    }
    if (blockIdx.x == 0) {
        __shared__ float s[256];
        int t = threadIdx.x;

        float v1 = (t < HH) ? b1[t] : 0.0f;
        s[t] = v1 * v1;
        __syncthreads();
        for (int o = 128; o > 0; o >>= 1) { if (t < o) s[t] += s[t + o]; __syncthreads(); }
        float nb2 = s[0];
        __syncthreads();
        {
            float nb = fmaxf(sqrtf(nb2), MINN);
            float th = tanhf(nb);
            float sc = th / nb;
            if (th > MAXN) { sc *= MAXN / th; th = MAXN; }
            if (t < HH) g_hb1[t] = sc * v1;
            if (t == 0) g_hb1sq = th * th;
        }

        float v3 = (t < DOUT) ? b3[t] : 0.0f;
        s[t] = v3 * v3;
        __syncthreads();
        for (int o = 128; o > 0; o >>= 1) { if (t < o) s[t] += s[t + o]; __syncthreads(); }
        nb2 = s[0];
        __syncthreads();
        {
            float nb = fmaxf(sqrtf(nb2), MINN);
            float th = tanhf(nb);
            float sc = th / nb;
            if (th > MAXN) { sc *= MAXN / th; th = MAXN; }
            if (t < DOUT) g_hb3[t] = sc * v3;
            if (t == 0) g_hb3sq = th * th;
        }
    }
}

extern __shared__ __align__(1024) char smraw[];

__global__ __launch_bounds__(TPB, 2)
void hnn_kernel(const float* __restrict__ X, float* __restrict__ out, int N, int nTiles)
{
    const u32 sb = (u32)__cvta_generic_to_shared(smraw);
    float* mxs  = (float*)(smraw + OFF_MXS);
    float* hb1s = (float*)(smraw + OFF_HB1);
    float* hb3s = (float*)(smraw + OFF_HB3);
    float* x2s  = (float*)(smraw + OFF_X2S);
    float* un_s = (float*)(smraw + OFF_UNS);

    const int tid = threadIdx.x;
    const int lane = tid & 31;
    const int c = tid >> 5;
    const int mg = c & 3;             // GEMM1 row group (32 rows)
    const int ng = c >> 2;            // GEMM1 col group
    const int rq = lane >> 2;         // row-quad within fragment
    const int cq = lane & 3;          // col-quad within fragment

    // W3 resident (staged once) + biases
    for (int i = tid; i < 1024; i += TPB) {
        int n = i >> 3, j = i & 7;
        cp_async16(sb + OFF_W3H + (u32)(n * 144 + j * 16), g_w3h + n * 64 + j * 8);
        cp_async16(sb + OFF_W3L + (u32)(n * 144 + j * 16), g_w3l + n * 64 + j * 8);
    }
    for (int i = tid; i < 64; i += TPB) hb1s[i] = (i < HH) ? g_hb1[i] : 0.0f;
    if (tid < DOUT) hb3s[tid] = g_hb3[tid];
    const float hb1sq = g_hb1sq;
    const float hb3sq = g_hb3sq;

    // GEMM1 B (W1) ldmatrix lane components
    const u32 bN   = (u32)(ng * 32 + ((lane >> 4) * 8) + (lane & 7));
    const u32 bKof = (u32)(((lane >> 3) & 1) * 16);
    // GEMM2 lane components
    const u32 a2H = sb + OFF_UH + (u32)((c * 16 + (lane & 15)) * 144 + (lane >> 4) * 16);
    const u32 a2L = a2H + 18432u;
    const u32 b2H = sb + OFF_W3H + (u32)((((lane >> 4) * 8) + (lane & 7)) * 144 + ((lane >> 3) & 1) * 16);
    const u32 b2L = b2H + 18432u;

    // W1 cp.async addressing (buffer-relative dst)
    u32 w1_rel[4];
    const __nv_bfloat16* w1_gsrc[4];
#pragma unroll
    for (int p = 0; p < 4; p++) {
        int u = tid + 256 * p;
        int half = u >> 9, n = (u >> 3) & 63, j = u & 7;
        w1_rel[p] = (u32)(half * 9216 + n * 144 + j * 16);
        w1_gsrc[p] = (half ? g_w1l : g_w1h) + n * 512 + j * 8;
    }

    for (int tile = blockIdx.x; tile < nTiles; tile += gridDim.x) {
        const int baseRow = tile * MT;

        __syncthreads();   // prior tile's GEMM2 reads (U alias of W1 bufs) complete

        // A-operand row pointers (fragment-direct): rows mg*32 + rq + {0,8,16,24}
        const float* prow[4];
#pragma unroll
        for (int j = 0; j < 4; j++) {
            int gr = baseRow + mg * 32 + j * 8 + rq;
            int grc = (gr < N) ? gr : (N - 1);
            prow[j] = X + (size_t)grc * DIN + 2 * cq;
        }

        float acc[2][4][4];
#pragma unroll
        for (int mt = 0; mt < 2; mt++)
#pragma unroll
            for (int nt = 0; nt < 4; nt++)
#pragma unroll
                for (int e = 0; e < 4; e++) acc[mt][nt][e] = 0.0f;
        float x2a[4] = {0.f, 0.f, 0.f, 0.f};

        // prologue: stage W1 chunk 0 -> buf0
#pragma unroll
        for (int p = 0; p < 4; p++)
            cp_async16(sb + w1_rel[p], w1_gsrc[p]);
        cp_wait_all();
        __syncthreads();

        // -------- GEMM1: x @ W1^T (HMMA bf16 3-way split, A direct from global) --------
        for (int kc = 0; kc < 8; kc++) {
            const u32 bW = sb + ((kc & 1) ? 18432u : 0u);
            if (kc < 7) {
                const u32 nW = sb + ((kc & 1) ? 0u : 18432u);
#pragma unroll
                for (int p = 0; p < 4; p++)
                    cp_async16(nW + w1_rel[p], w1_gsrc[p] + (kc + 1) * 64);
            }

#pragma unroll
            for (int k16 = 0; k16 < 4; k16++) {
                const int off = kc * 64 + k16 * 16;
                float2 v[8];
#pragma unroll
                for (int j = 0; j < 4; j++) {
                    v[2 * j]     = *(const float2*)(prow[j] + off);
                    v[2 * j + 1] = *(const float2*)(prow[j] + off + 8);
                }
                if (ng == 0) {
#pragma unroll
                    for (int j = 0; j < 4; j++) {
                        x2a[j] = fmaf(v[2 * j].x, v[2 * j].x, x2a[j]);
                        x2a[j] = fmaf(v[2 * j].y, v[2 * j].y, x2a[j]);
                        x2a[j] = fmaf(v[2 * j + 1].x, v[2 * j + 1].x, x2a[j]);
                        x2a[j] = fmaf(v[2 * j + 1].y, v[2 * j + 1].y, x2a[j]);
                    }
                }
                // fragment order: a0=(r,k0-7) a1=(r+8,k0-7) a2=(r,k8-15) a3=(r+8,k8-15)
                u32 ah[2][4], al[2][4];
                split2(v[0].x, v[0].y, ah[0][0], al[0][0]);
                split2(v[2].x, v[2].y, ah[0][1], al[0][1]);
                split2(v[1].x, v[1].y, ah[0][2], al[0][2]);
                split2(v[3].x, v[3].y, ah[0][3], al[0][3]);
                split2(v[4].x, v[4].y, ah[1][0], al[1][0]);
                split2(v[6].x, v[6].y, ah[1][1], al[1][1]);
                split2(v[5].x, v[5].y, ah[1][2], al[1][2]);
                split2(v[7].x, v[7].y, ah[1][3], al[1][3]);

                u32 bh[8], bl[8];
#pragma unroll
                for (int np = 0; np < 2; np++) {
                    u32 boff = (bN + (u32)(np * 16)) * 144u + (u32)(k16 * 32) + bKof;
                    ldsm4(bh + np * 4, bW + boff);
                    ldsm4(bl + np * 4, bW + 9216 + boff);
                }
#pragma unroll
                for (int mt = 0; mt < 2; mt++)
#pragma unroll
                    for (int nt = 0; nt < 4; nt++) {
                        mma_bf16(acc[mt][nt], ah[mt], bh + nt * 2);
                        mma_bf16(acc[mt][nt], al[mt], bh + nt * 2);
                        mma_bf16(acc[mt][nt], ah[mt], bl + nt * 2);
                    }
            }
            cp_wait_all();
            __syncthreads();
        }

        // x^2 quad-reduce (ng==0 warps own all rows of their mg group)
        if (ng == 0) {
#pragma unroll
            for (int h = 0; h < 4; h++) {
                float s = x2a[h];
                s += __shfl_xor_sync(0xffffffffu, s, 1);
                s += __shfl_xor_sync(0xffffffffu, s, 2);
                if (cq == 0) x2s[mg * 32 + h * 8 + rq] = s;
            }
        }

        // spill fragments to mxs [row][col], stride 65
        {
#pragma unroll
            for (int mt = 0; mt < 2; mt++) {
                int r0 = mg * 32 + mt * 16 + rq;
#pragma unroll
                for (int nt = 0; nt < 4; nt++) {
                    int col = ng * 32 + nt * 8 + cq * 2;
                    mxs[r0 * 65 + col]           = acc[mt][nt][0];
                    mxs[r0 * 65 + col + 1]       = acc[mt][nt][1];
                    mxs[(r0 + 8) * 65 + col]     = acc[mt][nt][2];
                    mxs[(r0 + 8) * 65 + col + 1] = acc[mt][nt][3];
                }
            }
        }
        __syncthreads();

        // -------- Epilogue 1 (threads 0..127, one per row) --------
        if (tid < 128) {
            const int r0 = tid;
            float sx2 = x2s[r0];
            float nx = fmaxf(sqrtf(sx2), MINN);
            float th = tanhf(nx);
            float al = th / nx;
            float xn1 = fmaxf(th, MINN);

            float p0 = 0.f, p1 = 0.f;
#pragma unroll
            for (int j = 0; j < HH; j++) {
                float v = al * mxs[r0 * 65 + j];
                p0 = fmaf(v, v, p0);
                p1 = fmaf(v, hb1s[j], p1);
            }
            float mxn = fmaxf(sqrtf(p0), MINN);
            float art = artanh_c(xn1);
            float t = tanhf(mxn / xn1 * art);
            float g = t / mxn;
            float rn = t;
            if (rn > MAXN) { g *= MAXN / rn; rn = MAXN; }
            float xy = g * p1;
            float x2 = rn * rn;
            float den = fmaxf(1.0f + 2.0f * xy + x2 * hb1sq, MINN);
            float A = (1.0f + 2.0f * xy + hb1sq) / den;
            float B = (1.0f - x2) / den;
            float nv2 = A * A * x2 + 2.0f * A * B * xy + B * B * hb1sq;
            float nv = sqrtf(nv2);
            float pf = (nv > MAXN) ? (MAXN / nv) : 1.0f;
            nv = fminf(nv, MAXN);
            float beta = artanh_c(nv) / fmaxf(nv, MINN);
            float C1a = beta * pf * A * g * al;
            float C2 = beta * pf * B;

            float xt_buf[HH];
            float p = 0.f;
#pragma unroll
            for (int j = 0; j < HH; j++) {
                float xt = C1a * mxs[r0 * 65 + j] + C2 * hb1s[j];
                xt = (xt > 0.0f) ? xt : 0.01f * xt;
                xt_buf[j] = xt;
                p = fmaf(xt, xt, p);
            }
            float nxt = fmaxf(sqrtf(p), MINN);
            float t3 = tanhf(nxt);
            float gam = t3 / nxt;
            if (t3 > MAXN) { gam *= MAXN / t3; t3 = MAXN; }
            un_s[r0] = fmaxf(t3, MINN);

            // u as bf16 hi/lo into ldmatrix layout (k padded to 64 with zeros)
#pragma unroll
            for (int jj = 0; jj < 25; jj++) {
                float v0 = gam * xt_buf[jj * 2];
                float v1 = (jj * 2 + 1 < HH) ? gam * xt_buf[jj * 2 + 1] : 0.0f;
                u32 h, l;
                split2(v0, v1, h, l);
                *(u32*)(smraw + OFF_UH + r0 * 144 + jj * 4) = h;
                *(u32*)(smraw + OFF_UL + r0 * 144 + jj * 4) = l;
            }
#pragma unroll
            for (int jj = 25; jj < 32; jj++) {
                *(u32*)(smraw + OFF_UH + r0 * 144 + jj * 4) = 0u;
                *(u32*)(smraw + OFF_UL + r0 * 144 + jj * 4) = 0u;
            }
        }
        __syncthreads();

        // -------- GEMM2: u @ W3^T (HMMA bf16, 3-way split; 16 rows/warp) --------
        float acc2[16][4];
#pragma unroll
        for (int nt = 0; nt < 16; nt++)
#pragma unroll
            for (int e = 0; e < 4; e++) acc2[nt][e] = 0.0f;

#pragma unroll
        for (int k16 = 0; k16 < 4; k16++) {
            u32 ah[4], al2[4];
            ldsm4(ah, a2H + (u32)(k16 * 32));
            ldsm4(al2, a2L + (u32)(k16 * 32));
#pragma unroll
            for (int np = 0; np < 8; np++) {
                u32 bh[4], bl[4];
                u32 boff = (u32)(np * 2304 + k16 * 32);
                ldsm4(bh, b2H + boff);
                ldsm4(bl, b2L + boff);
#pragma unroll
                for (int npi = 0; npi < 2; npi++) {
                    mma_bf16(acc2[np * 2 + npi], ah, bh + npi * 2);
                    mma_bf16(acc2[np * 2 + npi], al2, bh + npi * 2);
                    mma_bf16(acc2[np * 2 + npi], ah, bl + npi * 2);
                }
            }
        }

        float hb3v[32];
#pragma unroll
        for (int nt = 0; nt < 16; nt++) {
            float2 hv = *(float2*)(hb3s + nt * 8 + cq * 2);
            hb3v[nt * 2] = hv.x; hb3v[nt * 2 + 1] = hv.y;
        }
        float p0a = 0.f, p1a = 0.f, p0b = 0.f, p1b = 0.f;
#pragma unroll
        for (int nt = 0; nt < 16; nt++) {
            p0a = fmaf(acc2[nt][0], acc2[nt][0], fmaf(acc2[nt][1], acc2[nt][1], p0a));
            p1a = fmaf(acc2[nt][0], hb3v[nt * 2], fmaf(acc2[nt][1], hb3v[nt * 2 + 1], p1a));
            p0b = fmaf(acc2[nt][2], acc2[nt][2], fmaf(acc2[nt][3], acc2[nt][3], p0b));
            p1b = fmaf(acc2[nt][2], hb3v[nt * 2], fmaf(acc2[nt][3], hb3v[nt * 2 + 1], p1b));
        }
#pragma unroll
        for (int o = 1; o <= 2; o <<= 1) {
            p0a += __shfl_xor_sync(0xffffffffu, p0a, o);
            p1a += __shfl_xor_sync(0xffffffffu, p1a, o);
            p0b += __shfl_xor_sync(0xffffffffu, p0b, o);
            p1b += __shfl_xor_sync(0xffffffffu, p1b, o);
        }

        const int row1 = c * 16 + rq;
        const int row2 = row1 + 8;
        float cA1, cB1, cA2, cB2;
        {
            float un = un_s[row1];
            float mxn = fmaxf(sqrtf(p0a), MINN);
            float art = artanh_c(un);
            float t = tanhf(mxn / un * art);
            float g = t / mxn;
            float rn = t;
            if (rn > MAXN) { g *= MAXN / rn; rn = MAXN; }
            float xy = g * p1a;
            float x2 = rn * rn;
            float den = fmaxf(1.0f + 2.0f * xy + x2 * hb3sq, MINN);
            float A = (1.0f + 2.0f * xy + hb3sq) / den;
            float B = (1.0f - x2) / den;
            float nv = sqrtf(A * A * x2 + 2.0f * A * B * xy + B * B * hb3sq);
            float pf = (nv > MAXN) ? (MAXN / nv) : 1.0f;
            cA1 = pf * A * g; cB1 = pf * B;
        }
        {
            float un = un_s[row2];
            float mxn = fmaxf(sqrtf(p0b), MINN);
            float art = artanh_c(un);
            float t = tanhf(mxn / un * art);
            float g = t / mxn;
            float rn = t;
            if (rn > MAXN) { g *= MAXN / rn; rn = MAXN; }
            float xy = g * p1b;
            float x2 = rn * rn;
            float den = fmaxf(1.0f + 2.0f * xy + x2 * hb3sq, MINN);
            float A = (1.0f + 2.0f * xy + hb3sq) / den;
            float B = (1.0f - x2) / den;
            float nv = sqrtf(A * A * x2 + 2.0f * A * B * xy + B * B * hb3sq);
            float pf = (nv > MAXN) ? (MAXN / nv) : 1.0f;
            cA2 = pf * A * g; cB2 = pf * B;
        }

        {
            int g1r = baseRow + row1;
            int g2r = baseRow + row2;
            if (g1r < N) {
                float* o1 = out + (size_t)g1r * DOUT + cq * 2;
#pragma unroll
                for (int nt = 0; nt < 16; nt++) {
                    float2 v;
                    v.x = cA1 * acc2[nt][0] + cB1 * hb3v[nt * 2];
                    v.y = cA1 * acc2[nt][1] + cB1 * hb3v[nt * 2 + 1];
                    *(float2*)(o1 + nt * 8) = v;
                }
            }
            if (g2r < N) {
                float* o2 = out + (size_t)g2r * DOUT + cq * 2;
#pragma unroll
                for (int nt = 0; nt < 16; nt++) {
                    float2 v;
                    v.x = cA2 * acc2[nt][2] + cB2 * hb3v[nt * 2];
                    v.y = cA2 * acc2[nt][3] + cB2 * hb3v[nt * 2 + 1];
                    *(float2*)(o2 + nt * 8) = v;
                }
            }
        }
    }
}

extern "C" void kernel_launch(void* const* d_in, const int* in_sizes, int n_in,
                              void* d_out, int out_size) {
    const float* x  = (const float*)d_in[0];
    const float* W1 = (const float*)d_in[1];
    const float* b1 = (const float*)d_in[2];
    const float* W3 = (const float*)d_in[3];
    const float* b3 = (const float*)d_in[4];
    float* out = (float*)d_out;
    int N = in_sizes[0] / DIN;
    int nTiles = (N + MT - 1) / MT;
    int grid = nTiles < 296 ? nTiles : 296;

    cudaFuncSetAttribute(hnn_kernel, cudaFuncAttributeMaxDynamicSharedMemorySize, SMEM_BYTES);

    setup_kernel<<<161, 256>>>(W1, W3, b1, b3);
    hnn_kernel<<<grid, TPB, SMEM_BYTES>>>(x, out, N, nTiles);
}

// round 10
// speedup vs baseline: 1.0847x; 1.0231x over previous
#include <cuda_runtime.h>
#include <cuda_bf16.h>
#include <math.h>
#include <stdint.h>

#define TPB   256
#define MT    128
#define DIN   512
#define HH    50
#define DOUT  128
#define MAXN  0.996f
#define MINN  1e-15f

typedef unsigned long long ull;
typedef uint32_t u32;

// ---- smem byte offsets ----
// [0, 36864): W1 staging double buffer during GEMM1; U (bf16 hi/lo) after GEMM1.
#define OFF_UH    0
#define OFF_UL    18432
#define OFF_W3H   36864      // W3 hi 128x144 (resident)
#define OFF_W3L   55296
#define OFF_RED   73728      // 512 f32 exchange buffer (2048B)
#define OFF_HB1   75776      // 64 f32
#define OFF_HB3   76032      // 128 f32
#define OFF_X2S   76544      // 128 f32
#define OFF_UNS   77056      // 128 f32
#define SMEM_BYTES 77568

__device__ float g_hb1[64];
__device__ float g_hb3[128];
__device__ float g_hb1sq, g_hb3sq;
__device__ __align__(16) __nv_bfloat16 g_w1h[64 * 512];   // rows 50..63 zero
__device__ __align__(16) __nv_bfloat16 g_w1l[64 * 512];
__device__ __align__(16) __nv_bfloat16 g_w3h[128 * 64];   // k 50..63 zero
__device__ __align__(16) __nv_bfloat16 g_w3l[128 * 64];

__device__ __forceinline__ float artanh_c(float z) {
    z = fminf(z, 1.0f - 1e-7f);
    return 0.5f * logf((1.0f + z) / (1.0f - z));
}

// ---- HMMA / async helpers ----
__device__ __forceinline__ void mma_bf16(float* d, const u32* a, const u32* b) {
    asm("mma.sync.aligned.m16n8k16.row.col.f32.bf16.bf16.f32 "
        "{%0,%1,%2,%3}, {%4,%5,%6,%7}, {%8,%9}, {%0,%1,%2,%3};"
        : "+f"(d[0]), "+f"(d[1]), "+f"(d[2]), "+f"(d[3])
        : "r"(a[0]), "r"(a[1]), "r"(a[2]), "r"(a[3]), "r"(b[0]), "r"(b[1]));
}
__device__ __forceinline__ void ldsm4(u32* r, u32 addr) {
    asm volatile("ldmatrix.sync.aligned.m8n8.x4.shared.b16 {%0,%1,%2,%3}, [%4];"
        : "=r"(r[0]), "=r"(r[1]), "=r"(r[2]), "=r"(r[3]) : "r"(addr));
}
// truncation split of two floats -> packed bf16x2 hi (exact prefix) + bf16x2 lo
__device__ __forceinline__ void split2(float a, float b, u32& hi, u32& lo) {
    u32 ua = __float_as_uint(a), ub = __float_as_uint(b);
    u32 h;
    asm("prmt.b32 %0, %1, %2, 0x7632;" : "=r"(h) : "r"(ua), "r"(ub));
    float ha = __uint_as_float(ua & 0xFFFF0000u);
    float hb = __uint_as_float(ub & 0xFFFF0000u);
    float la = a - ha, lb = b - hb;
    u32 l;
    asm("cvt.rn.bf16x2.f32 %0, %1, %2;" : "=r"(l) : "f"(lb), "f"(la));
    hi = h; lo = l;
}
__device__ __forceinline__ void cp_async16(u32 sdst, const void* gsrc) {
    asm volatile("cp.async.ca.shared.global [%0], [%1], 16;" :: "r"(sdst), "l"(gsrc));
}
__device__ __forceinline__ void cp_wait_all() {
    asm volatile("cp.async.commit_group;\n\tcp.async.wait_group 0;" ::: "memory");
}

// merged setup: W1/W3 bf16 hi-lo conversion (grid-stride) + bias precompute (block 0)
__global__ void setup_kernel(const float* __restrict__ W1, const float* __restrict__ W3,
                             const float* __restrict__ b1, const float* __restrict__ b3) {
    for (int idx = blockIdx.x * blockDim.x + threadIdx.x;
         idx < 64 * 512 + 128 * 64; idx += gridDim.x * blockDim.x) {
        if (idx < 64 * 512) {
            int row = idx >> 9;
            float v = (row < HH) ? W1[(size_t)row * DIN + (idx & 511)] : 0.0f;
            u32 uh = __float_as_uint(v) & 0xFFFF0000u;
            g_w1h[idx] = __ushort_as_bfloat16((unsigned short)(uh >> 16));
            g_w1l[idx] = __float2bfloat16(v - __uint_as_float(uh));
        } else {
            int i = idx - 64 * 512;
            int k = i & 63;
            float v = (k < HH) ? W3[(size_t)(i >> 6) * HH + k] : 0.0f;
            u32 uh = __float_as_uint(v) & 0xFFFF0000u;
            g_w3h[i] = __ushort_as_bfloat16((unsigned short)(uh >> 16));
            g_w3l[i] = __float2bfloat16(v - __uint_as_float(uh));
        }
    }
    if (blockIdx.x == 0) {
        __shared__ float s[256];
        int t = threadIdx.x;

        float v1 = (t < HH) ? b1[t] : 0.0f;
        s[t] = v1 * v1;
        __syncthreads();
        for (int o = 128; o > 0; o >>= 1) { if (t < o) s[t] += s[t + o]; __syncthreads(); }
        float nb2 = s[0];
        __syncthreads();
        {
            float nb = fmaxf(sqrtf(nb2), MINN);
            float th = tanhf(nb);
            float sc = th / nb;
            if (th > MAXN) { sc *= MAXN / th; th = MAXN; }
            if (t < HH) g_hb1[t] = sc * v1;
            if (t == 0) g_hb1sq = th * th;
        }

        float v3 = (t < DOUT) ? b3[t] : 0.0f;
        s[t] = v3 * v3;
        __syncthreads();
        for (int o = 128; o > 0; o >>= 1) { if (t < o) s[t] += s[t + o]; __syncthreads(); }
        nb2 = s[0];
        __syncthreads();
        {
            float nb = fmaxf(sqrtf(nb2), MINN);
            float th = tanhf(nb);
            float sc = th / nb;
            if (th > MAXN) { sc *= MAXN / th; th = MAXN; }
            if (t < DOUT) g_hb3[t] = sc * v3;
            if (t == 0) g_hb3sq = th * th;
        }
    }
}

extern __shared__ __align__(1024) char smraw[];

__global__ __launch_bounds__(TPB, 2)
void hnn_kernel(const float* __restrict__ X, float* __restrict__ out, int N, int nTiles)
{
    const u32 sb = (u32)__cvta_generic_to_shared(smraw);
    float* hb1s = (float*)(smraw + OFF_HB1);
    float* hb3s = (float*)(smraw + OFF_HB3);
    float* red  = (float*)(smraw + OFF_RED);
    float* x2s  = (float*)(smraw + OFF_X2S);
    float* un_s = (float*)(smraw + OFF_UNS);

    const int tid = threadIdx.x;
    const int lane = tid & 31;
    const int c = tid >> 5;
    const int mg = c & 3;             // GEMM1 row group (32 rows)
    const int ng = c >> 2;            // GEMM1 col group
    const int rq = lane >> 2;         // row-quad within fragment
    const int cq = lane & 3;          // col-quad within fragment

    // W3 resident (staged once) + biases
    for (int i = tid; i < 1024; i += TPB) {
        int n = i >> 3, j = i & 7;
        cp_async16(sb + OFF_W3H + (u32)(n * 144 + j * 16), g_w3h + n * 64 + j * 8);
        cp_async16(sb + OFF_W3L + (u32)(n * 144 + j * 16), g_w3l + n * 64 + j * 8);
    }
    for (int i = tid; i < 64; i += TPB) hb1s[i] = (i < HH) ? g_hb1[i] : 0.0f;
    if (tid < DOUT) hb3s[tid] = g_hb3[tid];
    const float hb1sq = g_hb1sq;
    const float hb3sq = g_hb3sq;

    // GEMM1 B (W1) ldmatrix lane components
    const u32 bN   = (u32)(ng * 32 + ((lane >> 4) * 8) + (lane & 7));
    const u32 bKof = (u32)(((lane >> 3) & 1) * 16);
    // GEMM2 lane components
    const u32 a2H = sb + OFF_UH + (u32)((c * 16 + (lane & 15)) * 144 + (lane >> 4) * 16);
    const u32 a2L = a2H + 18432u;
    const u32 b2H = sb + OFF_W3H + (u32)((((lane >> 4) * 8) + (lane & 7)) * 144 + ((lane >> 3) & 1) * 16);
    const u32 b2L = b2H + 18432u;

    // W1 cp.async addressing (buffer-relative dst)
    u32 w1_rel[4];
    const __nv_bfloat16* w1_gsrc[4];
#pragma unroll
    for (int p = 0; p < 4; p++) {
        int u = tid + 256 * p;
        int half = u >> 9, n = (u >> 3) & 63, j = u & 7;
        w1_rel[p] = (u32)(half * 9216 + n * 144 + j * 16);
        w1_gsrc[p] = (half ? g_w1l : g_w1h) + n * 512 + j * 8;
    }

    // hb1 fragment values for this warp's columns (constant across tiles)
    float hb1v[8];
#pragma unroll
    for (int nt = 0; nt < 4; nt++) {
        // note: hb1s written above; safe to read after first __syncthreads below,
        // so defer the actual read into the loop prologue of the first tile.
        hb1v[nt * 2] = 0.f; hb1v[nt * 2 + 1] = 0.f;
    }
    bool hb1_loaded = false;

    for (int tile = blockIdx.x; tile < nTiles; tile += gridDim.x) {
        const int baseRow = tile * MT;

        __syncthreads();   // prior tile's GEMM2 reads (U alias of W1 bufs) complete

        if (!hb1_loaded) {
#pragma unroll
            for (int nt = 0; nt < 4; nt++) {
                float2 hv = *(float2*)(hb1s + ng * 32 + nt * 8 + cq * 2);
                hb1v[nt * 2] = hv.x; hb1v[nt * 2 + 1] = hv.y;
            }
            hb1_loaded = true;
        }

        // A-operand row pointers (fragment-direct): rows mg*32 + rq + {0,8,16,24}
        const float* prow[4];
#pragma unroll
        for (int j = 0; j < 4; j++) {
            int gr = baseRow + mg * 32 + j * 8 + rq;
            int grc = (gr < N) ? gr : (N - 1);
            prow[j] = X + (size_t)grc * DIN + 2 * cq;
        }

        float acc[2][4][4];
#pragma unroll
        for (int mt = 0; mt < 2; mt++)
#pragma unroll
            for (int nt = 0; nt < 4; nt++)
#pragma unroll
                for (int e = 0; e < 4; e++) acc[mt][nt][e] = 0.0f;
        float x2a[4] = {0.f, 0.f, 0.f, 0.f};

        // prologue: stage W1 chunk 0 -> buf0
#pragma unroll
        for (int p = 0; p < 4; p++)
            cp_async16(sb + w1_rel[p], w1_gsrc[p]);
        cp_wait_all();
        __syncthreads();

        // -------- GEMM1: x @ W1^T (HMMA bf16 3-way split, A direct from global) --------
        for (int kc = 0; kc < 8; kc++) {
            const u32 bW = sb + ((kc & 1) ? 18432u : 0u);
            if (kc < 7) {
                const u32 nW = sb + ((kc & 1) ? 0u : 18432u);
#pragma unroll
                for (int p = 0; p < 4; p++)
                    cp_async16(nW + w1_rel[p], w1_gsrc[p] + (kc + 1) * 64);
            }

#pragma unroll
            for (int k16 = 0; k16 < 4; k16++) {
                const int off = kc * 64 + k16 * 16;
                float2 v[8];
#pragma unroll
                for (int j = 0; j < 4; j++) {
                    v[2 * j]     = *(const float2*)(prow[j] + off);
                    v[2 * j + 1] = *(const float2*)(prow[j] + off + 8);
                }
                if (ng == 0) {
#pragma unroll
                    for (int j = 0; j < 4; j++) {
                        x2a[j] = fmaf(v[2 * j].x, v[2 * j].x, x2a[j]);
                        x2a[j] = fmaf(v[2 * j].y, v[2 * j].y, x2a[j]);
                        x2a[j] = fmaf(v[2 * j + 1].x, v[2 * j + 1].x, x2a[j]);
                        x2a[j] = fmaf(v[2 * j + 1].y, v[2 * j + 1].y, x2a[j]);
                    }
                }
                u32 ah[2][4], al[2][4];
                split2(v[0].x, v[0].y, ah[0][0], al[0][0]);
                split2(v[2].x, v[2].y, ah[0][1], al[0][1]);
                split2(v[1].x, v[1].y, ah[0][2], al[0][2]);
                split2(v[3].x, v[3].y, ah[0][3], al[0][3]);
                split2(v[4].x, v[4].y, ah[1][0], al[1][0]);
                split2(v[6].x, v[6].y, ah[1][1], al[1][1]);
                split2(v[5].x, v[5].y, ah[1][2], al[1][2]);
                split2(v[7].x, v[7].y, ah[1][3], al[1][3]);

                u32 bh[8], bl[8];
#pragma unroll
                for (int np = 0; np < 2; np++) {
                    u32 boff = (bN + (u32)(np * 16)) * 144u + (u32)(k16 * 32) + bKof;
                    ldsm4(bh + np * 4, bW + boff);
                    ldsm4(bl + np * 4, bW + 9216 + boff);
                }
#pragma unroll
                for (int mt = 0; mt < 2; mt++)
#pragma unroll
                    for (int nt = 0; nt < 4; nt++) {
                        mma_bf16(acc[mt][nt], ah[mt], bh + nt * 2);
                        mma_bf16(acc[mt][nt], al[mt], bh + nt * 2);
                        mma_bf16(acc[mt][nt], ah[mt], bl + nt * 2);
                    }
            }
            cp_wait_all();
            __syncthreads();
        }

        // -------- Epilogue 1, fully in fragments --------
        // raw partial sums S0 = sum(v^2), S1 = sum(v*hb1) per row-slot
        float S0[4], S1[4];
#pragma unroll
        for (int mt = 0; mt < 2; mt++)
#pragma unroll
            for (int h = 0; h < 2; h++) {
                int s = mt * 2 + h;
                float a0 = 0.f, a1 = 0.f;
#pragma unroll
                for (int nt = 0; nt < 4; nt++) {
                    float v0 = acc[mt][nt][2 * h], v1 = acc[mt][nt][2 * h + 1];
                    a0 = fmaf(v0, v0, fmaf(v1, v1, a0));
                    a1 = fmaf(v0, hb1v[2 * nt], fmaf(v1, hb1v[2 * nt + 1], a1));
                }
                S0[s] = a0; S1[s] = a1;
            }
#pragma unroll
        for (int s = 0; s < 4; s++) {
            S0[s] += __shfl_xor_sync(~0u, S0[s], 1);
            S0[s] += __shfl_xor_sync(~0u, S0[s], 2);
            S1[s] += __shfl_xor_sync(~0u, S1[s], 1);
            S1[s] += __shfl_xor_sync(~0u, S1[s], 2);
        }
        // x^2 quad-reduce (ng==0 warps own all rows of their mg group)
        if (ng == 0) {
#pragma unroll
            for (int h = 0; h < 4; h++) {
                float s2 = x2a[h];
                s2 += __shfl_xor_sync(0xffffffffu, s2, 1);
                s2 += __shfl_xor_sync(0xffffffffu, s2, 2);
                if (cq == 0) x2s[mg * 32 + h * 8 + rq] = s2;
            }
        }
        if (cq == 0) {
#pragma unroll
            for (int s = 0; s < 4; s++) {
                int row = mg * 32 + (s >> 1) * 16 + (s & 1) * 8 + rq;
                red[ng * 256 + row] = S0[s];
                red[ng * 256 + 128 + row] = S1[s];
            }
        }
        __syncthreads();
        float S0r[4], S1r[4], sx2v[4];
#pragma unroll
        for (int s = 0; s < 4; s++) {
            int row = mg * 32 + (s >> 1) * 16 + (s & 1) * 8 + rq;
            S0r[s] = red[row] + red[256 + row];
            S1r[s] = red[128 + row] + red[384 + row];
            sx2v[s] = x2s[row];
        }
        __syncthreads();   // red free for reuse

        // per-slot coefficient chain (redundant across the 4 cq lanes + 2 ng warps)
        float C1a[4], C2c[4];
#pragma unroll
        for (int s = 0; s < 4; s++) {
            float nx = fmaxf(sqrtf(sx2v[s]), MINN);
            float th = tanhf(nx);
            float al = th / nx;
            float xn1 = fmaxf(th, MINN);
            float p0 = al * al * S0r[s];
            float p1 = al * S1r[s];
            float mxn = fmaxf(sqrtf(p0), MINN);
            float art = artanh_c(xn1);
            float t = tanhf(mxn / xn1 * art);
            float g = t / mxn;
            float rn = t;
            if (rn > MAXN) { g *= MAXN / rn; rn = MAXN; }
            float xy = g * p1;
            float x2 = rn * rn;
            float den = fmaxf(1.0f + 2.0f * xy + x2 * hb1sq, MINN);
            float A = (1.0f + 2.0f * xy + hb1sq) / den;
            float B = (1.0f - x2) / den;
            float nv2 = A * A * x2 + 2.0f * A * B * xy + B * B * hb1sq;
            float nv = sqrtf(nv2);
            float pf = (nv > MAXN) ? (MAXN / nv) : 1.0f;
            nv = fminf(nv, MAXN);
            float beta = artanh_c(nv) / fmaxf(nv, MINN);
            C1a[s] = beta * pf * A * g * al;
            C2c[s] = beta * pf * B;
        }

        // LeakyReLU in place on fragments + sum(xt^2)
        float Q[4] = {0.f, 0.f, 0.f, 0.f};
#pragma unroll
        for (int mt = 0; mt < 2; mt++)
#pragma unroll
            for (int nt = 0; nt < 4; nt++)
#pragma unroll
                for (int h = 0; h < 2; h++) {
                    int s = mt * 2 + h;
                    float xt0 = C1a[s] * acc[mt][nt][2 * h]     + C2c[s] * hb1v[2 * nt];
                    float xt1 = C1a[s] * acc[mt][nt][2 * h + 1] + C2c[s] * hb1v[2 * nt + 1];
                    xt0 = (xt0 > 0.0f) ? xt0 : 0.01f * xt0;
                    xt1 = (xt1 > 0.0f) ? xt1 : 0.01f * xt1;
                    acc[mt][nt][2 * h] = xt0;
                    acc[mt][nt][2 * h + 1] = xt1;
                    Q[s] = fmaf(xt0, xt0, fmaf(xt1, xt1, Q[s]));
                }
#pragma unroll
        for (int s = 0; s < 4; s++) {
            Q[s] += __shfl_xor_sync(~0u, Q[s], 1);
            Q[s] += __shfl_xor_sync(~0u, Q[s], 2);
        }
        if (cq == 0) {
#pragma unroll
            for (int s = 0; s < 4; s++) {
                int row = mg * 32 + (s >> 1) * 16 + (s & 1) * 8 + rq;
                red[ng * 128 + row] = Q[s];
            }
        }
        __syncthreads();
        float gam[4];
#pragma unroll
        for (int s = 0; s < 4; s++) {
            int row = mg * 32 + (s >> 1) * 16 + (s & 1) * 8 + rq;
            float q = red[row] + red[128 + row];
            float nxt = fmaxf(sqrtf(q), MINN);
            float t3 = tanhf(nxt);
            float gm = t3 / nxt;
            if (t3 > MAXN) { gm *= MAXN / t3; t3 = MAXN; }
            gam[s] = gm;
            if (ng == 0 && cq == 0) un_s[row] = fmaxf(t3, MINN);
        }

        // write u = gam * xt straight from fragments as bf16 hi/lo (ldmatrix layout)
#pragma unroll
        for (int mt = 0; mt < 2; mt++) {
            int r0 = mg * 32 + mt * 16 + rq;
#pragma unroll
            for (int nt = 0; nt < 4; nt++) {
                u32 coff = (u32)((ng * 32 + nt * 8 + cq * 2) * 2);
                u32 h, l;
                split2(gam[mt * 2] * acc[mt][nt][0], gam[mt * 2] * acc[mt][nt][1], h, l);
                *(u32*)(smraw + OFF_UH + r0 * 144 + coff) = h;
                *(u32*)(smraw + OFF_UL + r0 * 144 + coff) = l;
                split2(gam[mt * 2 + 1] * acc[mt][nt][2], gam[mt * 2 + 1] * acc[mt][nt][3], h, l);
                *(u32*)(smraw + OFF_UH + (r0 + 8) * 144 + coff) = h;
                *(u32*)(smraw + OFF_UL + (r0 + 8) * 144 + coff) = l;
            }
        }
        // pad columns 50..63 of U were never produced by any warp? ng=1 covers cols 32..63:
        // acc raw = 0 there (W1 pad) and hb1v = 0 -> xt = 0 -> u = 0, written above. OK.
        __syncthreads();

        // -------- GEMM2: u @ W3^T (HMMA bf16, 3-way split; 16 rows/warp) --------
        float acc2[16][4];
#pragma unroll
        for (int nt = 0; nt < 16; nt++)
#pragma unroll
            for (int e = 0; e < 4; e++) acc2[nt][e] = 0.0f;

#pragma unroll
        for (int k16 = 0; k16 < 4; k16++) {
            u32 ah[4], al2[4];
            ldsm4(ah, a2H + (u32)(k16 * 32));
            ldsm4(al2, a2L + (u32)(k16 * 32));
#pragma unroll
            for (int np = 0; np < 8; np++) {
                u32 bh[4], bl[4];
                u32 boff = (u32)(np * 2304 + k16 * 32);
                ldsm4(bh, b2H + boff);
                ldsm4(bl, b2L + boff);
#pragma unroll
                for (int npi = 0; npi < 2; npi++) {
                    mma_bf16(acc2[np * 2 + npi], ah, bh + npi * 2);
                    mma_bf16(acc2[np * 2 + npi], al2, bh + npi * 2);
                    mma_bf16(acc2[np * 2 + npi], ah, bl + npi * 2);
                }
            }
        }

        float hb3v[32];
#pragma unroll
        for (int nt = 0; nt < 16; nt++) {
            float2 hv = *(float2*)(hb3s + nt * 8 + cq * 2);
            hb3v[nt * 2] = hv.x; hb3v[nt * 2 + 1] = hv.y;
        }
        float p0a = 0.f, p1a = 0.f, p0b = 0.f, p1b = 0.f;
#pragma unroll
        for (int nt = 0; nt < 16; nt++) {
            p0a = fmaf(acc2[nt][0], acc2[nt][0], fmaf(acc2[nt][1], acc2[nt][1], p0a));
            p1a = fmaf(acc2[nt][0], hb3v[nt * 2], fmaf(acc2[nt][1], hb3v[nt * 2 + 1], p1a));
            p0b = fmaf(acc2[nt][2], acc2[nt][2], fmaf(acc2[nt][3], acc2[nt][3], p0b));
            p1b = fmaf(acc2[nt][2], hb3v[nt * 2], fmaf(acc2[nt][3], hb3v[nt * 2 + 1], p1b));
        }
#pragma unroll
        for (int o = 1; o <= 2; o <<= 1) {
            p0a += __shfl_xor_sync(0xffffffffu, p0a, o);
            p1a += __shfl_xor_sync(0xffffffffu, p1a, o);
            p0b += __shfl_xor_sync(0xffffffffu, p0b, o);
            p1b += __shfl_xor_sync(0xffffffffu, p1b, o);
        }

        const int row1 = c * 16 + rq;
        const int row2 = row1 + 8;
        float cA1, cB1, cA2, cB2;
        {
            float un = un_s[row1];
            float mxn = fmaxf(sqrtf(p0a), MINN);
            float art = artanh_c(un);
            float t = tanhf(mxn / un * art);
            float g = t / mxn;
            float rn = t;
            if (rn > MAXN) { g *= MAXN / rn; rn = MAXN; }
            float xy = g * p1a;
            float x2 = rn * rn;
            float den = fmaxf(1.0f + 2.0f * xy + x2 * hb3sq, MINN);
            float A = (1.0f + 2.0f * xy + hb3sq) / den;
            float B = (1.0f - x2) / den;
            float nv = sqrtf(A * A * x2 + 2.0f * A * B * xy + B * B * hb3sq);
            float pf = (nv > MAXN) ? (MAXN / nv) : 1.0f;
            cA1 = pf * A * g; cB1 = pf * B;
        }
        {
            float un = un_s[row2];
            float mxn = fmaxf(sqrtf(p0b), MINN);
            float art = artanh_c(un);
            float t = tanhf(mxn / un * art);
            float g = t / mxn;
            float rn = t;
            if (rn > MAXN) { g *= MAXN / rn; rn = MAXN; }
            float xy = g * p1b;
            float x2 = rn * rn;
            float den = fmaxf(1.0f + 2.0f * xy + x2 * hb3sq, MINN);
            float A = (1.0f + 2.0f * xy + hb3sq) / den;
            float B = (1.0f - x2) / den;
            float nv = sqrtf(A * A * x2 + 2.0f * A * B * xy + B * B * hb3sq);
            float pf = (nv > MAXN) ? (MAXN / nv) : 1.0f;
            cA2 = pf * A * g; cB2 = pf * B;
        }

        {
            int g1r = baseRow + row1;
            int g2r = baseRow + row2;
            if (g1r < N) {
                float* o1 = out + (size_t)g1r * DOUT + cq * 2;
#pragma unroll
                for (int nt = 0; nt < 16; nt++) {
                    float2 v;
                    v.x = cA1 * acc2[nt][0] + cB1 * hb3v[nt * 2];
                    v.y = cA1 * acc2[nt][1] + cB1 * hb3v[nt * 2 + 1];
                    *(float2*)(o1 + nt * 8) = v;
                }
            }
            if (g2r < N) {
                float* o2 = out + (size_t)g2r * DOUT + cq * 2;
#pragma unroll
                for (int nt = 0; nt < 16; nt++) {
                    float2 v;
                    v.x = cA2 * acc2[nt][2] + cB2 * hb3v[nt * 2];
                    v.y = cA2 * acc2[nt][3] + cB2 * hb3v[nt * 2 + 1];
                    *(float2*)(o2 + nt * 8) = v;
                }
            }
        }
    }
}

extern "C" void kernel_launch(void* const* d_in, const int* in_sizes, int n_in,
                              void* d_out, int out_size) {
    const float* x  = (const float*)d_in[0];
    const float* W1 = (const float*)d_in[1];
    const float* b1 = (const float*)d_in[2];
    const float* W3 = (const float*)d_in[3];
    const float* b3 = (const float*)d_in[4];
    float* out = (float*)d_out;
    int N = in_sizes[0] / DIN;
    int nTiles = (N + MT - 1) / MT;
    int grid = nTiles < 296 ? nTiles : 296;

    cudaFuncSetAttribute(hnn_kernel, cudaFuncAttributeMaxDynamicSharedMemorySize, SMEM_BYTES);

    setup_kernel<<<161, 256>>>(W1, W3, b1, b3);
    hnn_kernel<<<grid, TPB, SMEM_BYTES>>>(x, out, N, nTiles);
}

// round 11
// speedup vs baseline: 1.1134x; 1.0265x over previous
#include <cuda_runtime.h>
#include <cuda_bf16.h>
#include <math.h>
#include <stdint.h>

#define TPB   256
#define MT    128
#define DIN   512
#define HH    50
#define DOUT  128
#define MAXN  0.996f
#define MINN  1e-15f

typedef unsigned long long ull;
typedef uint32_t u32;

// ---- smem byte offsets ----
// [0, 36864): W1 staging double buffer during GEMM1; U (bf16 hi/lo) after GEMM1.
#define OFF_UH    0
#define OFF_UL    18432
#define OFF_W3H   36864      // W3 hi 128x144 (resident)
#define OFF_W3L   55296
#define OFF_RED   73728      // 512 f32 exchange buffer (2048B)
#define OFF_HB1   75776      // 64 f32
#define OFF_HB3   76032      // 128 f32
#define OFF_X2S   76544      // 128 f32
#define OFF_UNS   77056      // 128 f32
#define SMEM_BYTES 77568

__device__ float g_hb1[64];
__device__ float g_hb3[128];
__device__ float g_hb1sq, g_hb3sq;
__device__ __align__(16) __nv_bfloat16 g_w1h[64 * 512];   // rows 50..63 zero
__device__ __align__(16) __nv_bfloat16 g_w1l[64 * 512];
__device__ __align__(16) __nv_bfloat16 g_w3h[128 * 64];   // k 50..63 zero
__device__ __align__(16) __nv_bfloat16 g_w3l[128 * 64];

__device__ __forceinline__ float artanh_c(float z) {
    z = fminf(z, 1.0f - 1e-7f);
    return 0.5f * logf((1.0f + z) / (1.0f - z));
}

// ---- HMMA / async helpers ----
__device__ __forceinline__ void mma_bf16(float* d, const u32* a, const u32* b) {
    asm("mma.sync.aligned.m16n8k16.row.col.f32.bf16.bf16.f32 "
        "{%0,%1,%2,%3}, {%4,%5,%6,%7}, {%8,%9}, {%0,%1,%2,%3};"
        : "+f"(d[0]), "+f"(d[1]), "+f"(d[2]), "+f"(d[3])
        : "r"(a[0]), "r"(a[1]), "r"(a[2]), "r"(a[3]), "r"(b[0]), "r"(b[1]));
}
__device__ __forceinline__ void ldsm4(u32* r, u32 addr) {
    asm volatile("ldmatrix.sync.aligned.m8n8.x4.shared.b16 {%0,%1,%2,%3}, [%4];"
        : "=r"(r[0]), "=r"(r[1]), "=r"(r[2]), "=r"(r[3]) : "r"(addr));
}
// truncation split of two floats -> packed bf16x2 hi (exact prefix) + bf16x2 lo
__device__ __forceinline__ void split2(float a, float b, u32& hi, u32& lo) {
    u32 ua = __float_as_uint(a), ub = __float_as_uint(b);
    u32 h;
    asm("prmt.b32 %0, %1, %2, 0x7632;" : "=r"(h) : "r"(ua), "r"(ub));
    float ha = __uint_as_float(ua & 0xFFFF0000u);
    float hb = __uint_as_float(ub & 0xFFFF0000u);
    float la = a - ha, lb = b - hb;
    u32 l;
    asm("cvt.rn.bf16x2.f32 %0, %1, %2;" : "=r"(l) : "f"(lb), "f"(la));
    hi = h; lo = l;
}
__device__ __forceinline__ void cp_async16(u32 sdst, const void* gsrc) {
    asm volatile("cp.async.ca.shared.global [%0], [%1], 16;" :: "r"(sdst), "l"(gsrc));
}
__device__ __forceinline__ void cp_wait_all() {
    asm volatile("cp.async.commit_group;\n\tcp.async.wait_group 0;" ::: "memory");
}

// merged setup: W1/W3 bf16 hi-lo conversion (grid-stride) + bias precompute (block 0)
__global__ void setup_kernel(const float* __restrict__ W1, const float* __restrict__ W3,
                             const float* __restrict__ b1, const float* __restrict__ b3) {
    for (int idx = blockIdx.x * blockDim.x + threadIdx.x;
         idx < 64 * 512 + 128 * 64; idx += gridDim.x * blockDim.x) {
        if (idx < 64 * 512) {
            int row = idx >> 9;
            float v = (row < HH) ? W1[(size_t)row * DIN + (idx & 511)] : 0.0f;
            u32 uh = __float_as_uint(v) & 0xFFFF0000u;
            g_w1h[idx] = __ushort_as_bfloat16((unsigned short)(uh >> 16));
            g_w1l[idx] = __float2bfloat16(v - __uint_as_float(uh));
        } else {
            int i = idx - 64 * 512;
            int k = i & 63;
            float v = (k < HH) ? W3[(size_t)(i >> 6) * HH + k] : 0.0f;
            u32 uh = __float_as_uint(v) & 0xFFFF0000u;
            g_w3h[i] = __ushort_as_bfloat16((unsigned short)(uh >> 16));
            g_w3l[i] = __float2bfloat16(v - __uint_as_float(uh));
        }
    }
    if (blockIdx.x == 0) {
        __shared__ float s[256];
        int t = threadIdx.x;

        float v1 = (t < HH) ? b1[t] : 0.0f;
        s[t] = v1 * v1;
        __syncthreads();
        for (int o = 128; o > 0; o >>= 1) { if (t < o) s[t] += s[t + o]; __syncthreads(); }
        float nb2 = s[0];
        __syncthreads();
        {
            float nb = fmaxf(sqrtf(nb2), MINN);
            float th = tanhf(nb);
            float sc = th / nb;
            if (th > MAXN) { sc *= MAXN / th; th = MAXN; }
            if (t < HH) g_hb1[t] = sc * v1;
            if (t == 0) g_hb1sq = th * th;
        }

        float v3 = (t < DOUT) ? b3[t] : 0.0f;
        s[t] = v3 * v3;
        __syncthreads();
        for (int o = 128; o > 0; o >>= 1) { if (t < o) s[t] += s[t + o]; __syncthreads(); }
        nb2 = s[0];
        __syncthreads();
        {
            float nb = fmaxf(sqrtf(nb2), MINN);
            float th = tanhf(nb);
            float sc = th / nb;
            if (th > MAXN) { sc *= MAXN / th; th = MAXN; }
            if (t < DOUT) g_hb3[t] = sc * v3;
            if (t == 0) g_hb3sq = th * th;
        }
    }
}

extern __shared__ __align__(1024) char smraw[];

__global__ __launch_bounds__(TPB, 2)
void hnn_kernel(const float* __restrict__ X, float* __restrict__ out, int N, int nTiles)
{
    const u32 sb = (u32)__cvta_generic_to_shared(smraw);
    float* hb1s = (float*)(smraw + OFF_HB1);
    float* hb3s = (float*)(smraw + OFF_HB3);
    float* red  = (float*)(smraw + OFF_RED);
    float* x2s  = (float*)(smraw + OFF_X2S);
    float* un_s = (float*)(smraw + OFF_UNS);

    const int tid = threadIdx.x;
    const int lane = tid & 31;
    const int c = tid >> 5;
    const int mg = c & 3;             // GEMM1 row group (32 rows)
    const int ng = c >> 2;            // GEMM1 col group
    const int rq = lane >> 2;         // row-quad within fragment
    const int cq = lane & 3;          // col-quad within fragment

    // W3 resident (staged once) + biases
    for (int i = tid; i < 1024; i += TPB) {
        int n = i >> 3, j = i & 7;
        cp_async16(sb + OFF_W3H + (u32)(n * 144 + j * 16), g_w3h + n * 64 + j * 8);
        cp_async16(sb + OFF_W3L + (u32)(n * 144 + j * 16), g_w3l + n * 64 + j * 8);
    }
    for (int i = tid; i < 64; i += TPB) hb1s[i] = (i < HH) ? g_hb1[i] : 0.0f;
    if (tid < DOUT) hb3s[tid] = g_hb3[tid];
    const float hb1sq = g_hb1sq;
    const float hb3sq = g_hb3sq;

    // GEMM1 B (W1) ldmatrix lane components
    const u32 bN   = (u32)(ng * 32 + ((lane >> 4) * 8) + (lane & 7));
    const u32 bKof = (u32)(((lane >> 3) & 1) * 16);
    // GEMM2 lane components
    const u32 a2H = sb + OFF_UH + (u32)((c * 16 + (lane & 15)) * 144 + (lane >> 4) * 16);
    const u32 a2L = a2H + 18432u;
    const u32 b2H = sb + OFF_W3H + (u32)((((lane >> 4) * 8) + (lane & 7)) * 144 + ((lane >> 3) & 1) * 16);
    const u32 b2L = b2H + 18432u;

    // W1 cp.async addressing (buffer-relative dst)
    u32 w1_rel[4];
    const __nv_bfloat16* w1_gsrc[4];
#pragma unroll
    for (int p = 0; p < 4; p++) {
        int u = tid + 256 * p;
        int half = u >> 9, n = (u >> 3) & 63, j = u & 7;
        w1_rel[p] = (u32)(half * 9216 + n * 144 + j * 16);
        w1_gsrc[p] = (half ? g_w1l : g_w1h) + n * 512 + j * 8;
    }

    float hb1v[8];
    bool hb1_loaded = false;

    for (int tile = blockIdx.x; tile < nTiles; tile += gridDim.x) {
        const int baseRow = tile * MT;

        __syncthreads();   // prior tile's GEMM2 reads (U alias of W1 bufs) complete

        if (!hb1_loaded) {
#pragma unroll
            for (int nt = 0; nt < 4; nt++) {
                float2 hv = *(float2*)(hb1s + ng * 32 + nt * 8 + cq * 2);
                hb1v[nt * 2] = hv.x; hb1v[nt * 2 + 1] = hv.y;
            }
            hb1_loaded = true;
        }

        // A-operand row pointers (fragment-direct): rows mg*32 + rq + {0,8,16,24}
        const float* prow[4];
#pragma unroll
        for (int j = 0; j < 4; j++) {
            int gr = baseRow + mg * 32 + j * 8 + rq;
            int grc = (gr < N) ? gr : (N - 1);
            prow[j] = X + (size_t)grc * DIN + 2 * cq;
        }

        float acc[2][4][4];
#pragma unroll
        for (int mt = 0; mt < 2; mt++)
#pragma unroll
            for (int nt = 0; nt < 4; nt++)
#pragma unroll
                for (int e = 0; e < 4; e++) acc[mt][nt][e] = 0.0f;
        float x2a[4] = {0.f, 0.f, 0.f, 0.f};

        // prologue: stage W1 chunk 0 -> buf0; preload x fragments for k16 step 0
#pragma unroll
        for (int p = 0; p < 4; p++)
            cp_async16(sb + w1_rel[p], w1_gsrc[p]);
        float2 v[8];
#pragma unroll
        for (int j = 0; j < 4; j++) {
            v[2 * j]     = *(const float2*)(prow[j]);
            v[2 * j + 1] = *(const float2*)(prow[j] + 8);
        }
        cp_wait_all();
        __syncthreads();

        // -------- GEMM1: x @ W1^T (HMMA bf16 3-way split, A direct from global,
        //          register-prefetch pipeline on A) --------
        for (int kc = 0; kc < 8; kc++) {
            const u32 bW = sb + ((kc & 1) ? 18432u : 0u);
            if (kc < 7) {
                const u32 nW = sb + ((kc & 1) ? 0u : 18432u);
#pragma unroll
                for (int p = 0; p < 4; p++)
                    cp_async16(nW + w1_rel[p], w1_gsrc[p] + (kc + 1) * 64);
            }

#pragma unroll
            for (int k16 = 0; k16 < 4; k16++) {
                // prefetch next k16 step's fragments (next kc's step 0 across boundary)
                float2 vn[8];
                const bool last = (kc == 7) && (k16 == 3);
                if (!last) {
                    const int noff = (k16 < 3) ? (kc * 64 + (k16 + 1) * 16)
                                               : ((kc + 1) * 64);
#pragma unroll
                    for (int j = 0; j < 4; j++) {
                        vn[2 * j]     = *(const float2*)(prow[j] + noff);
                        vn[2 * j + 1] = *(const float2*)(prow[j] + noff + 8);
                    }
                }

                if (ng == 0) {
#pragma unroll
                    for (int j = 0; j < 4; j++) {
                        x2a[j] = fmaf(v[2 * j].x, v[2 * j].x, x2a[j]);
                        x2a[j] = fmaf(v[2 * j].y, v[2 * j].y, x2a[j]);
                        x2a[j] = fmaf(v[2 * j + 1].x, v[2 * j + 1].x, x2a[j]);
                        x2a[j] = fmaf(v[2 * j + 1].y, v[2 * j + 1].y, x2a[j]);
                    }
                }
                u32 ah[2][4], al[2][4];
                split2(v[0].x, v[0].y, ah[0][0], al[0][0]);
                split2(v[2].x, v[2].y, ah[0][1], al[0][1]);
                split2(v[1].x, v[1].y, ah[0][2], al[0][2]);
                split2(v[3].x, v[3].y, ah[0][3], al[0][3]);
                split2(v[4].x, v[4].y, ah[1][0], al[1][0]);
                split2(v[6].x, v[6].y, ah[1][1], al[1][1]);
                split2(v[5].x, v[5].y, ah[1][2], al[1][2]);
                split2(v[7].x, v[7].y, ah[1][3], al[1][3]);

                u32 bh[8], bl[8];
#pragma unroll
                for (int np = 0; np < 2; np++) {
                    u32 boff = (bN + (u32)(np * 16)) * 144u + (u32)(k16 * 32) + bKof;
                    ldsm4(bh + np * 4, bW + boff);
                    ldsm4(bl + np * 4, bW + 9216 + boff);
                }
#pragma unroll
                for (int mt = 0; mt < 2; mt++)
#pragma unroll
                    for (int nt = 0; nt < 4; nt++) {
                        mma_bf16(acc[mt][nt], ah[mt], bh + nt * 2);
                        mma_bf16(acc[mt][nt], al[mt], bh + nt * 2);
                        mma_bf16(acc[mt][nt], ah[mt], bl + nt * 2);
                    }

                if (!last) {
#pragma unroll
                    for (int j = 0; j < 8; j++) v[j] = vn[j];
                }
            }
            cp_wait_all();
            __syncthreads();
        }

        // -------- Epilogue 1, fully in fragments --------
        float S0[4], S1[4];
#pragma unroll
        for (int mt = 0; mt < 2; mt++)
#pragma unroll
            for (int h = 0; h < 2; h++) {
                int s = mt * 2 + h;
                float a0 = 0.f, a1 = 0.f;
#pragma unroll
                for (int nt = 0; nt < 4; nt++) {
                    float v0 = acc[mt][nt][2 * h], v1 = acc[mt][nt][2 * h + 1];
                    a0 = fmaf(v0, v0, fmaf(v1, v1, a0));
                    a1 = fmaf(v0, hb1v[2 * nt], fmaf(v1, hb1v[2 * nt + 1], a1));
                }
                S0[s] = a0; S1[s] = a1;
            }
#pragma unroll
        for (int s = 0; s < 4; s++) {
            S0[s] += __shfl_xor_sync(~0u, S0[s], 1);
            S0[s] += __shfl_xor_sync(~0u, S0[s], 2);
            S1[s] += __shfl_xor_sync(~0u, S1[s], 1);
            S1[s] += __shfl_xor_sync(~0u, S1[s], 2);
        }
        if (ng == 0) {
#pragma unroll
            for (int h = 0; h < 4; h++) {
                float s2 = x2a[h];
                s2 += __shfl_xor_sync(0xffffffffu, s2, 1);
                s2 += __shfl_xor_sync(0xffffffffu, s2, 2);
                if (cq == 0) x2s[mg * 32 + h * 8 + rq] = s2;
            }
        }
        if (cq == 0) {
#pragma unroll
            for (int s = 0; s < 4; s++) {
                int row = mg * 32 + (s >> 1) * 16 + (s & 1) * 8 + rq;
                red[ng * 256 + row] = S0[s];
                red[ng * 256 + 128 + row] = S1[s];
            }
        }
        __syncthreads();
        float S0r[4], S1r[4], sx2v[4];
#pragma unroll
        for (int s = 0; s < 4; s++) {
            int row = mg * 32 + (s >> 1) * 16 + (s & 1) * 8 + rq;
            S0r[s] = red[row] + red[256 + row];
            S1r[s] = red[128 + row] + red[384 + row];
            sx2v[s] = x2s[row];
        }
        __syncthreads();   // red free for reuse

        float C1a[4], C2c[4];
#pragma unroll
        for (int s = 0; s < 4; s++) {
            float nx = fmaxf(sqrtf(sx2v[s]), MINN);
            float th = tanhf(nx);
            float al = th / nx;
            float xn1 = fmaxf(th, MINN);
            float p0 = al * al * S0r[s];
            float p1 = al * S1r[s];
            float mxn = fmaxf(sqrtf(p0), MINN);
            float art = artanh_c(xn1);
            float t = tanhf(mxn / xn1 * art);
            float g = t / mxn;
            float rn = t;
            if (rn > MAXN) { g *= MAXN / rn; rn = MAXN; }
            float xy = g * p1;
            float x2 = rn * rn;
            float den = fmaxf(1.0f + 2.0f * xy + x2 * hb1sq, MINN);
            float A = (1.0f + 2.0f * xy + hb1sq) / den;
            float B = (1.0f - x2) / den;
            float nv2 = A * A * x2 + 2.0f * A * B * xy + B * B * hb1sq;
            float nv = sqrtf(nv2);
            float pf = (nv > MAXN) ? (MAXN / nv) : 1.0f;
            nv = fminf(nv, MAXN);
            float beta = artanh_c(nv) / fmaxf(nv, MINN);
            C1a[s] = beta * pf * A * g * al;
            C2c[s] = beta * pf * B;
        }

        float Q[4] = {0.f, 0.f, 0.f, 0.f};
#pragma unroll
        for (int mt = 0; mt < 2; mt++)
#pragma unroll
            for (int nt = 0; nt < 4; nt++)
#pragma unroll
                for (int h = 0; h < 2; h++) {
                    int s = mt * 2 + h;
                    float xt0 = C1a[s] * acc[mt][nt][2 * h]     + C2c[s] * hb1v[2 * nt];
                    float xt1 = C1a[s] * acc[mt][nt][2 * h + 1] + C2c[s] * hb1v[2 * nt + 1];
                    xt0 = (xt0 > 0.0f) ? xt0 : 0.01f * xt0;
                    xt1 = (xt1 > 0.0f) ? xt1 : 0.01f * xt1;
                    acc[mt][nt][2 * h] = xt0;
                    acc[mt][nt][2 * h + 1] = xt1;
                    Q[s] = fmaf(xt0, xt0, fmaf(xt1, xt1, Q[s]));
                }
#pragma unroll
        for (int s = 0; s < 4; s++) {
            Q[s] += __shfl_xor_sync(~0u, Q[s], 1);
            Q[s] += __shfl_xor_sync(~0u, Q[s], 2);
        }
        if (cq == 0) {
#pragma unroll
            for (int s = 0; s < 4; s++) {
                int row = mg * 32 + (s >> 1) * 16 + (s & 1) * 8 + rq;
                red[ng * 128 + row] = Q[s];
            }
        }
        __syncthreads();
        float gam[4];
#pragma unroll
        for (int s = 0; s < 4; s++) {
            int row = mg * 32 + (s >> 1) * 16 + (s & 1) * 8 + rq;
            float q = red[row] + red[128 + row];
            float nxt = fmaxf(sqrtf(q), MINN);
            float t3 = tanhf(nxt);
            float gm = t3 / nxt;
            if (t3 > MAXN) { gm *= MAXN / t3; t3 = MAXN; }
            gam[s] = gm;
            if (ng == 0 && cq == 0) un_s[row] = fmaxf(t3, MINN);
        }

        // write u = gam * xt straight from fragments as bf16 hi/lo (ldmatrix layout)
#pragma unroll
        for (int mt = 0; mt < 2; mt++) {
            int r0 = mg * 32 + mt * 16 + rq;
#pragma unroll
            for (int nt = 0; nt < 4; nt++) {
                u32 coff = (u32)((ng * 32 + nt * 8 + cq * 2) * 2);
                u32 h, l;
                split2(gam[mt * 2] * acc[mt][nt][0], gam[mt * 2] * acc[mt][nt][1], h, l);
                *(u32*)(smraw + OFF_UH + r0 * 144 + coff) = h;
                *(u32*)(smraw + OFF_UL + r0 * 144 + coff) = l;
                split2(gam[mt * 2 + 1] * acc[mt][nt][2], gam[mt * 2 + 1] * acc[mt][nt][3], h, l);
                *(u32*)(smraw + OFF_UH + (r0 + 8) * 144 + coff) = h;
                *(u32*)(smraw + OFF_UL + (r0 + 8) * 144 + coff) = l;
            }
        }
        __syncthreads();

        // -------- GEMM2: u @ W3^T (HMMA bf16, 3-way split; 16 rows/warp) --------
        float acc2[16][4];
#pragma unroll
        for (int nt = 0; nt < 16; nt++)
#pragma unroll
            for (int e = 0; e < 4; e++) acc2[nt][e] = 0.0f;

#pragma unroll
        for (int k16 = 0; k16 < 4; k16++) {
            u32 ah[4], al2[4];
            ldsm4(ah, a2H + (u32)(k16 * 32));
            ldsm4(al2, a2L + (u32)(k16 * 32));
#pragma unroll
            for (int np = 0; np < 8; np++) {
                u32 bh[4], bl[4];
                u32 boff = (u32)(np * 2304 + k16 * 32);
                ldsm4(bh, b2H + boff);
                ldsm4(bl, b2L + boff);
#pragma unroll
                for (int npi = 0; npi < 2; npi++) {
                    mma_bf16(acc2[np * 2 + npi], ah, bh + npi * 2);
                    mma_bf16(acc2[np * 2 + npi], al2, bh + npi * 2);
                    mma_bf16(acc2[np * 2 + npi], ah, bl + npi * 2);
                }
            }
        }

        // row sums; hb3 read from smem (saves 32 regs vs register-resident copy)
        float p0a = 0.f, p1a = 0.f, p0b = 0.f, p1b = 0.f;
#pragma unroll
        for (int nt = 0; nt < 16; nt++) {
            float2 hv = *(float2*)(hb3s + nt * 8 + cq * 2);
            p0a = fmaf(acc2[nt][0], acc2[nt][0], fmaf(acc2[nt][1], acc2[nt][1], p0a));
            p1a = fmaf(acc2[nt][0], hv.x, fmaf(acc2[nt][1], hv.y, p1a));
            p0b = fmaf(acc2[nt][2], acc2[nt][2], fmaf(acc2[nt][3], acc2[nt][3], p0b));
            p1b = fmaf(acc2[nt][2], hv.x, fmaf(acc2[nt][3], hv.y, p1b));
        }
#pragma unroll
        for (int o = 1; o <= 2; o <<= 1) {
            p0a += __shfl_xor_sync(0xffffffffu, p0a, o);
            p1a += __shfl_xor_sync(0xffffffffu, p1a, o);
            p0b += __shfl_xor_sync(0xffffffffu, p0b, o);
            p1b += __shfl_xor_sync(0xffffffffu, p1b, o);
        }

        const int row1 = c * 16 + rq;
        const int row2 = row1 + 8;
        float cA1, cB1, cA2, cB2;
        {
            float un = un_s[row1];
            float mxn = fmaxf(sqrtf(p0a), MINN);
            float art = artanh_c(un);
            float t = tanhf(mxn / un * art);
            float g = t / mxn;
            float rn = t;
            if (rn > MAXN) { g *= MAXN / rn; rn = MAXN; }
            float xy = g * p1a;
            float x2 = rn * rn;
            float den = fmaxf(1.0f + 2.0f * xy + x2 * hb3sq, MINN);
            float A = (1.0f + 2.0f * xy + hb3sq) / den;
            float B = (1.0f - x2) / den;
            float nv = sqrtf(A * A * x2 + 2.0f * A * B * xy + B * B * hb3sq);
            float pf = (nv > MAXN) ? (MAXN / nv) : 1.0f;
            cA1 = pf * A * g; cB1 = pf * B;
        }
        {
            float un = un_s[row2];
            float mxn = fmaxf(sqrtf(p0b), MINN);
            float art = artanh_c(un);
            float t = tanhf(mxn / un * art);
            float g = t / mxn;
            float rn = t;
            if (rn > MAXN) { g *= MAXN / rn; rn = MAXN; }
            float xy = g * p1b;
            float x2 = rn * rn;
            float den = fmaxf(1.0f + 2.0f * xy + x2 * hb3sq, MINN);
            float A = (1.0f + 2.0f * xy + hb3sq) / den;
            float B = (1.0f - x2) / den;
            float nv = sqrtf(A * A * x2 + 2.0f * A * B * xy + B * B * hb3sq);
            float pf = (nv > MAXN) ? (MAXN / nv) : 1.0f;
            cA2 = pf * A * g; cB2 = pf * B;
        }

        {
            int g1r = baseRow + row1;
            int g2r = baseRow + row2;
            if (g1r < N) {
                float* o1 = out + (size_t)g1r * DOUT + cq * 2;
#pragma unroll
                for (int nt = 0; nt < 16; nt++) {
                    float2 hv = *(float2*)(hb3s + nt * 8 + cq * 2);
                    float2 vv;
                    vv.x = cA1 * acc2[nt][0] + cB1 * hv.x;
                    vv.y = cA1 * acc2[nt][1] + cB1 * hv.y;
                    *(float2*)(o1 + nt * 8) = vv;
                }
            }
            if (g2r < N) {
                float* o2 = out + (size_t)g2r * DOUT + cq * 2;
#pragma unroll
                for (int nt = 0; nt < 16; nt++) {
                    float2 hv = *(float2*)(hb3s + nt * 8 + cq * 2);
                    float2 vv;
                    vv.x = cA2 * acc2[nt][2] + cB2 * hv.x;
                    vv.y = cA2 * acc2[nt][3] + cB2 * hv.y;
                    *(float2*)(o2 + nt * 8) = vv;
                }
            }
        }
    }
}

extern "C" void kernel_launch(void* const* d_in, const int* in_sizes, int n_in,
                              void* d_out, int out_size) {
    const float* x  = (const float*)d_in[0];
    const float* W1 = (const float*)d_in[1];
    const float* b1 = (const float*)d_in[2];
    const float* W3 = (const float*)d_in[3];
    const float* b3 = (const float*)d_in[4];
    float* out = (float*)d_out;
    int N = in_sizes[0] / DIN;
    int nTiles = (N + MT - 1) / MT;
    int grid = nTiles < 296 ? nTiles : 296;

    cudaFuncSetAttribute(hnn_kernel, cudaFuncAttributeMaxDynamicSharedMemorySize, SMEM_BYTES);

    setup_kernel<<<161, 256>>>(W1, W3, b1, b3);
    hnn_kernel<<<grid, TPB, SMEM_BYTES>>>(x, out, N, nTiles);
}